// round 1
// baseline (speedup 1.0000x reference)
#include <cuda_runtime.h>

// ============================================================================
// PointNet++ part-seg forward, hand-rolled for GB300 (sm_103a).
// Pipeline: split -> 4x SA(FPS,kNN20,group,MLP,maxpool) -> 4x FP(3NN interp,
// concat, MLP) -> seg head -> transpose(g0).
// All scratch in one __device__ arena (no allocations). All launches on the
// default stream; graph-capturable.
// ============================================================================

#define BB 8
#define NN 4096
#define KK 20   // kNN neighbors in SA blocks

// ---- float arena offsets --------------------------------------------------
#define OFF_XYZ   0
#define SZ_PTS    (BB*NN*3)                     // 98304
#define OFF_NRM   (OFF_XYZ + SZ_PTS)
#define OFF_X1    (OFF_NRM + SZ_PTS)
#define OFF_X2    (OFF_X1 + BB*512*3)
#define OFF_X3    (OFF_X2 + BB*256*3)
#define OFF_X4    (OFF_X3 + BB*128*3)
#define OFF_F1    (OFF_X4 + BB*64*3)
#define OFF_F2    (OFF_F1 + BB*512*64)
#define OFF_F3    (OFF_F2 + BB*256*128)
#define OFF_F4    (OFF_F3 + BB*128*256)
#define OFF_G3    (OFF_F4 + BB*64*512)
#define OFF_G2    (OFF_G3 + BB*128*512)
#define OFF_G1    (OFF_G2 + BB*256*256)
#define OFF_G0    (OFF_G1 + BB*512*128)
#define OFF_GRP   (OFF_G0 + BB*NN*128)
#define OFF_H     (OFF_GRP + 2744320)           // max grouped tile (SA2)
#define OFF_CAT   (OFF_H + 5242880)             // pre-pool MLP output (all SA equal)
#define ARENA_SZ  (OFF_CAT + 4915200)           // max cat (FP0)

__device__ float g_arena[ARENA_SZ];
__device__ int   g_iarena[4096 + BB*512*KK];    // fps idx + knn idx

// ---------------------------------------------------------------------------
// split x [B,6,N] -> xyz [B,N,3], nrm [B,N,3]
// ---------------------------------------------------------------------------
__global__ void split_kernel(const float* __restrict__ x,
                             float* __restrict__ xyz, float* __restrict__ nrm) {
    int i = blockIdx.x * blockDim.x + threadIdx.x;
    if (i >= BB * NN) return;
    int b = i / NN, n = i - b * NN;
    const float* base = x + (long)b * 6 * NN;
#pragma unroll
    for (int j = 0; j < 3; j++) {
        xyz[(long)i * 3 + j] = base[(long)j * NN + n];
        nrm[(long)i * 3 + j] = base[(long)(3 + j) * NN + n];
    }
}

// ---------------------------------------------------------------------------
// Furthest point sampling. One block (256 thr) per batch. Matches JAX scan:
//   out[0]=0; repeat: emit far, dist=min(dist,d(.,far)), far=argmax(dist)
// Tie-break: first (smallest) index, matching jnp.argmax.
// ---------------------------------------------------------------------------
template <int PTS>
__global__ void fps_kernel(const float* __restrict__ xyz, int Npts, int S,
                           int* __restrict__ outIdx, float* __restrict__ outXyz) {
    int b = blockIdx.x;
    int t = threadIdx.x;
    const float* base = xyz + (long)b * Npts * 3;
    float px[PTS], py[PTS], pz[PTS], dist[PTS];
#pragma unroll
    for (int i = 0; i < PTS; i++) {
        int p = i * 256 + t;
        if (p < Npts) {
            px[i] = base[p * 3 + 0];
            py[i] = base[p * 3 + 1];
            pz[i] = base[p * 3 + 2];
            dist[i] = 1e10f;
        } else {
            px[i] = py[i] = pz[i] = 0.f;
            dist[i] = -1e30f;
        }
    }
    __shared__ float s_val[8];
    __shared__ int   s_idx[8];
    __shared__ int   s_far;
    int far = 0;
    for (int it = 0; it < S; ++it) {
        if (t == 0) {
            outIdx[b * S + it] = far;
            outXyz[((long)b * S + it) * 3 + 0] = base[far * 3 + 0];
            outXyz[((long)b * S + it) * 3 + 1] = base[far * 3 + 1];
            outXyz[((long)b * S + it) * 3 + 2] = base[far * 3 + 2];
        }
        float fx = base[far * 3 + 0];
        float fy = base[far * 3 + 1];
        float fz = base[far * 3 + 2];
        float bestv = -1e30f; int besti = 0;
#pragma unroll
        for (int i = 0; i < PTS; i++) {
            float dx = px[i] - fx, dy = py[i] - fy, dz = pz[i] - fz;
            float d = fmaf(dz, dz, fmaf(dy, dy, dx * dx));
            dist[i] = fminf(dist[i], d);
            if (dist[i] > bestv) { bestv = dist[i]; besti = i * 256 + t; }
        }
#pragma unroll
        for (int o = 16; o > 0; o >>= 1) {
            float ov = __shfl_down_sync(0xffffffffu, bestv, o);
            int   oi = __shfl_down_sync(0xffffffffu, besti, o);
            if (ov > bestv || (ov == bestv && oi < besti)) { bestv = ov; besti = oi; }
        }
        if ((t & 31) == 0) { s_val[t >> 5] = bestv; s_idx[t >> 5] = besti; }
        __syncthreads();
        if (t == 0) {
            float v = s_val[0]; int bi = s_idx[0];
#pragma unroll
            for (int w = 1; w < 8; w++)
                if (s_val[w] > v || (s_val[w] == v && s_idx[w] < bi)) { v = s_val[w]; bi = s_idx[w]; }
            s_far = bi;
        }
        __syncthreads();
        far = s_far;
    }
}

// ---------------------------------------------------------------------------
// kNN (K=20) via expanded distance |q|^2 - 2 q.r + |r|^2 (matches ref knn()).
// One thread per query; shared tiles of refs. Ties -> smaller index.
// ---------------------------------------------------------------------------
__global__ void knn_kernel(const float* __restrict__ q, int S,
                           const float* __restrict__ ref, int M,
                           int* __restrict__ out) {
    const int TILE = 512;
    __shared__ float sx[TILE], sy[TILE], sz[TILE], sr[TILE];
    int nqb = (S + 127) / 128;
    int b  = blockIdx.x / nqb;
    int qi = (blockIdx.x % nqb) * 128 + threadIdx.x;
    bool valid = qi < S;
    float qx = 0, qy = 0, qz = 0, qq = 0;
    if (valid) {
        const float* qp = q + ((long)b * S + qi) * 3;
        qx = qp[0]; qy = qp[1]; qz = qp[2];
        qq = qx * qx + qy * qy + qz * qz;
    }
    float bd[KK]; int bi[KK];
#pragma unroll
    for (int j = 0; j < KK; j++) { bd[j] = 3.4e38f; bi[j] = 0; }
    const float* rbase = ref + (long)b * M * 3;
    for (int m0 = 0; m0 < M; m0 += TILE) {
        int lim = min(TILE, M - m0);
        for (int j = threadIdx.x; j < lim; j += blockDim.x) {
            float rx = rbase[(m0 + j) * 3 + 0];
            float ry = rbase[(m0 + j) * 3 + 1];
            float rz = rbase[(m0 + j) * 3 + 2];
            sx[j] = rx; sy[j] = ry; sz[j] = rz;
            sr[j] = rx * rx + ry * ry + rz * rz;
        }
        __syncthreads();
        if (valid) {
            for (int mm = 0; mm < lim; mm++) {
                float dot = qx * sx[mm] + qy * sy[mm] + qz * sz[mm];
                float d = qq - 2.f * dot + sr[mm];
                if (d < bd[KK - 1]) {
                    int p = KK - 1;
                    while (p > 0 && bd[p - 1] > d) { bd[p] = bd[p - 1]; bi[p] = bi[p - 1]; --p; }
                    bd[p] = d; bi[p] = m0 + mm;
                }
            }
        }
        __syncthreads();
    }
    if (valid) {
        int* op = out + ((long)b * S + qi) * KK;
#pragma unroll
        for (int j = 0; j < KK; j++) op[j] = bi[j];
    }
}

// ---------------------------------------------------------------------------
// Build grouped tile: grp[b,s,k,0:3] = ref[nidx]-new ; grp[...,3:] = feats[nidx]
// ---------------------------------------------------------------------------
__global__ void group_kernel(const float* __restrict__ newxyz,
                             const float* __restrict__ refxyz,
                             const float* __restrict__ feats,
                             const int* __restrict__ knn,
                             float* __restrict__ grp,
                             int S, int M, int C, int total) {
    int Cin = C + 3;
    int stride = gridDim.x * blockDim.x;
    for (int i = blockIdx.x * blockDim.x + threadIdx.x; i < total; i += stride) {
        int c = i % Cin;
        int r = i / Cin;               // (b*S+s)*KK + k
        int nb = knn[r];
        int s2 = r / KK;               // b*S+s
        int b  = s2 / S;
        float v;
        if (c < 3)
            v = refxyz[((long)b * M + nb) * 3 + c] - newxyz[(long)s2 * 3 + c];
        else
            v = feats[((long)b * M + nb) * C + (c - 3)];
        grp[i] = v;
    }
}

// ---------------------------------------------------------------------------
// Row-tiled GEMM: out[r][d] = act(sum_c A[r][c]*W[c][d] + bias[d])
// 16 rows per block in shared; each thread computes 2 output channels (float2).
// ---------------------------------------------------------------------------
__global__ void gemm_kernel(const float* __restrict__ A, const float* __restrict__ W,
                            const float* __restrict__ bias, float* __restrict__ out,
                            int rows, int Cin, int Cout, int relu) {
    extern __shared__ float sh[];
    const int RT = 16;
    int row0 = blockIdx.x * RT;
    for (int i = threadIdx.x; i < RT * Cin; i += blockDim.x) {
        int r = i / Cin, c = i - r * Cin;
        int row = row0 + r;
        sh[i] = (row < rows) ? A[(long)row * Cin + c] : 0.f;
    }
    __syncthreads();
    int d0 = (blockIdx.y * blockDim.x + threadIdx.x) * 2;
    if (d0 >= Cout) return;
    float2 acc[RT];
#pragma unroll
    for (int r = 0; r < RT; r++) acc[r] = make_float2(0.f, 0.f);
    for (int c = 0; c < Cin; c++) {
        float2 w = *reinterpret_cast<const float2*>(W + (long)c * Cout + d0);
        const float* shc = sh + c;
#pragma unroll
        for (int r = 0; r < RT; r++) {
            float v = shc[r * Cin];
            acc[r].x = fmaf(v, w.x, acc[r].x);
            acc[r].y = fmaf(v, w.y, acc[r].y);
        }
    }
    float2 bb = *reinterpret_cast<const float2*>(bias + d0);
#pragma unroll
    for (int r = 0; r < RT; r++) {
        int row = row0 + r;
        if (row < rows) {
            float vx = acc[r].x + bb.x, vy = acc[r].y + bb.y;
            if (relu) { vx = fmaxf(vx, 0.f); vy = fmaxf(vy, 0.f); }
            *reinterpret_cast<float2*>(out + (long)row * Cout + d0) = make_float2(vx, vy);
        }
    }
}

// ---------------------------------------------------------------------------
// Max-pool over K neighbors: f[bs,d] = max_k h[bs*K+k, d]
// ---------------------------------------------------------------------------
__global__ void maxpool_kernel(const float* __restrict__ h, float* __restrict__ f,
                               int total, int C) {
    int stride = gridDim.x * blockDim.x;
    for (int i = blockIdx.x * blockDim.x + threadIdx.x; i < total; i += stride) {
        int d = i % C;
        long bs = i / C;
        const float* p = h + (bs * KK) * (long)C + d;
        float m = p[0];
#pragma unroll
        for (int k = 1; k < KK; k++) m = fmaxf(m, p[(long)k * C]);
        f[i] = m;
    }
}

// ---------------------------------------------------------------------------
// 3-NN interpolation (FP block front half): selection via expanded distance
// (matches ref knn), weights via direct squared diff (matches ref fp_block).
// Writes interp into cat[:, 0:C].
// ---------------------------------------------------------------------------
__global__ void interp3_kernel(const float* __restrict__ xq, int Sq,
                               const float* __restrict__ xr, int Mr,
                               const float* __restrict__ fr, int C,
                               float* __restrict__ cat, int Ct) {
    int gid = blockIdx.x * blockDim.x + threadIdx.x;
    if (gid >= BB * Sq) return;
    int b = gid / Sq, s = gid - b * Sq;
    const float* qp = xq + ((long)b * Sq + s) * 3;
    float qx = qp[0], qy = qp[1], qz = qp[2];
    float qq = qx * qx + qy * qy + qz * qz;
    float bd0 = 3.4e38f, bd1 = 3.4e38f, bd2 = 3.4e38f;
    int bi0 = 0, bi1 = 0, bi2 = 0;
    const float* rp = xr + (long)b * Mr * 3;
    for (int m = 0; m < Mr; m++) {
        float rx = rp[m * 3 + 0], ry = rp[m * 3 + 1], rz = rp[m * 3 + 2];
        float rr = rx * rx + ry * ry + rz * rz;
        float d = qq - 2.f * (qx * rx + qy * ry + qz * rz) + rr;
        if (d < bd2) {
            if (d < bd1) {
                if (d < bd0) { bd2 = bd1; bi2 = bi1; bd1 = bd0; bi1 = bi0; bd0 = d; bi0 = m; }
                else         { bd2 = bd1; bi2 = bi1; bd1 = d; bi1 = m; }
            } else           { bd2 = d; bi2 = m; }
        }
    }
    int bi[3] = { bi0, bi1, bi2 };
    float w[3]; float ws = 0.f;
#pragma unroll
    for (int j = 0; j < 3; j++) {
        const float* pp = rp + bi[j] * 3;
        float dx = pp[0] - qx, dy = pp[1] - qy, dz = pp[2] - qz;
        float dd = dx * dx + dy * dy + dz * dz;
        w[j] = 1.f / (dd + 1e-8f);
        ws += w[j];
    }
#pragma unroll
    for (int j = 0; j < 3; j++) w[j] = w[j] / ws;
    const float* f0p = fr + ((long)b * Mr + bi[0]) * C;
    const float* f1p = fr + ((long)b * Mr + bi[1]) * C;
    const float* f2p = fr + ((long)b * Mr + bi[2]) * C;
    long ro = ((long)b * Sq + s) * Ct;
    for (int c = 0; c < C; c++)
        cat[ro + c] = w[0] * f0p[c] + w[1] * f1p[c] + w[2] * f2p[c];
}

// copy skip features into cat at column offset `off`
__global__ void copy_skip_kernel(const float* __restrict__ src, float* __restrict__ cat,
                                 int rows, int Cs, int Ct, int off) {
    int total = rows * Cs;
    int stride = gridDim.x * blockDim.x;
    for (int i = blockIdx.x * blockDim.x + threadIdx.x; i < total; i += stride) {
        int row = i / Cs, c = i - row * Cs;
        cat[(long)row * Ct + off + c] = src[(long)row * Cs + c];
    }
}

// FP0 skip: [cls(16) | xyz(3) | nrm(3)] into cat0[:, 128:150]
__global__ void fp0_skip_kernel(const float* __restrict__ cls,
                                const float* __restrict__ xyz,
                                const float* __restrict__ nrm,
                                float* __restrict__ cat) {
    int total = BB * NN * 22;
    int stride = gridDim.x * blockDim.x;
    for (int i = blockIdx.x * blockDim.x + threadIdx.x; i < total; i += stride) {
        int c = i % 22;
        int row = i / 22;
        int b = row / NN;
        float v;
        if (c < 16)      v = cls[b * 16 + c];
        else if (c < 19) v = xyz[(long)row * 3 + (c - 16)];
        else             v = nrm[(long)row * 3 + (c - 19)];
        cat[(long)row * 150 + 128 + c] = v;
    }
}

// g0 [B,N,128] -> out [B,128,N]
__global__ void transpose_kernel(const float* __restrict__ in, float* __restrict__ out) {
    __shared__ float tile[32][33];
    int b = blockIdx.z;
    int n0 = blockIdx.x * 32, c0 = blockIdx.y * 32;
    int tx = threadIdx.x, ty = threadIdx.y;
    tile[ty][tx] = in[((long)b * NN + n0 + ty) * 128 + c0 + tx];
    __syncthreads();
    out[((long)b * 128 + c0 + ty) * NN + n0 + tx] = tile[tx][ty];
}

// ============================================================================
// host driver
// ============================================================================
static void launch_gemm(const float* A, const float* W, const float* bias, float* out,
                        int rows, int Cin, int Cout, int relu) {
    int bd = (Cout >= 256) ? 128 : ((Cout >= 128) ? 64 : 32);
    dim3 g((rows + 15) / 16, (Cout + bd * 2 - 1) / (bd * 2));
    gemm_kernel<<<g, bd, 16 * Cin * sizeof(float)>>>(A, W, bias, out, rows, Cin, Cout, relu);
}

extern "C" void kernel_launch(void* const* d_in, const int* in_sizes, int n_in,
                              void* d_out, int out_size) {
    const float* x    = (const float*)d_in[0];
    const float* cls  = (const float*)d_in[1];
    const float* W0 = (const float*)d_in[2];  const float* b0 = (const float*)d_in[3];
    const float* W1 = (const float*)d_in[4];  const float* b1 = (const float*)d_in[5];
    const float* W2 = (const float*)d_in[6];  const float* b2 = (const float*)d_in[7];
    const float* W3 = (const float*)d_in[8];  const float* b3 = (const float*)d_in[9];
    const float* F3 = (const float*)d_in[10]; const float* fb3 = (const float*)d_in[11];
    const float* F2 = (const float*)d_in[12]; const float* fb2 = (const float*)d_in[13];
    const float* F1 = (const float*)d_in[14]; const float* fb1 = (const float*)d_in[15];
    const float* F0 = (const float*)d_in[16]; const float* fb0 = (const float*)d_in[17];
    const float* Wseg = (const float*)d_in[18]; const float* bseg = (const float*)d_in[19];

    float* arena = 0; int* iar = 0;
    cudaGetSymbolAddress((void**)&arena, g_arena);
    cudaGetSymbolAddress((void**)&iar, g_iarena);

    float* xyz = arena + OFF_XYZ;
    float* nrm = arena + OFF_NRM;
    float* x1 = arena + OFF_X1; float* x2 = arena + OFF_X2;
    float* x3 = arena + OFF_X3; float* x4 = arena + OFF_X4;
    float* f1 = arena + OFF_F1; float* f2 = arena + OFF_F2;
    float* f3 = arena + OFF_F3; float* f4 = arena + OFF_F4;
    float* g3 = arena + OFF_G3; float* g2 = arena + OFF_G2;
    float* g1 = arena + OFF_G1; float* g0 = arena + OFF_G0;
    float* grp = arena + OFF_GRP;
    float* hbuf = arena + OFF_H;
    float* cat  = arena + OFF_CAT;
    int* fidx = iar;
    int* knn  = iar + 4096;

    split_kernel<<<(BB * NN + 255) / 256, 256>>>(x, xyz, nrm);

    // ---- SA1: 4096 -> 512, feats = nrm (C=3), W0: 6->64 ----
    fps_kernel<16><<<BB, 256>>>(xyz, NN, 512, fidx, x1);
    knn_kernel<<<BB * ((512 + 127) / 128), 128>>>(x1, 512, xyz, NN, knn);
    {
        int total = BB * 512 * KK * 6;
        group_kernel<<<(total + 255) / 256, 256>>>(x1, xyz, nrm, knn, grp, 512, NN, 3, total);
        launch_gemm(grp, W0, b0, hbuf, BB * 512 * KK, 6, 64, 1);
        int pt = BB * 512 * 64;
        maxpool_kernel<<<(pt + 255) / 256, 256>>>(hbuf, f1, pt, 64);
    }
    // ---- SA2: 512 -> 256, feats = f1 (C=64), W1: 67->128 ----
    fps_kernel<2><<<BB, 256>>>(x1, 512, 256, fidx, x2);
    knn_kernel<<<BB * ((256 + 127) / 128), 128>>>(x2, 256, x1, 512, knn);
    {
        int total = BB * 256 * KK * 67;
        group_kernel<<<(total + 255) / 256, 256>>>(x2, x1, f1, knn, grp, 256, 512, 64, total);
        launch_gemm(grp, W1, b1, hbuf, BB * 256 * KK, 67, 128, 1);
        int pt = BB * 256 * 128;
        maxpool_kernel<<<(pt + 255) / 256, 256>>>(hbuf, f2, pt, 128);
    }
    // ---- SA3: 256 -> 128, feats = f2 (C=128), W2: 131->256 ----
    fps_kernel<1><<<BB, 256>>>(x2, 256, 128, fidx, x3);
    knn_kernel<<<BB, 128>>>(x3, 128, x2, 256, knn);
    {
        int total = BB * 128 * KK * 131;
        group_kernel<<<(total + 255) / 256, 256>>>(x3, x2, f2, knn, grp, 128, 256, 128, total);
        launch_gemm(grp, W2, b2, hbuf, BB * 128 * KK, 131, 256, 1);
        int pt = BB * 128 * 256;
        maxpool_kernel<<<(pt + 255) / 256, 256>>>(hbuf, f3, pt, 256);
    }
    // ---- SA4: 128 -> 64, feats = f3 (C=256), W3: 259->512 ----
    fps_kernel<1><<<BB, 256>>>(x3, 128, 64, fidx, x4);
    knn_kernel<<<BB, 128>>>(x4, 64, x3, 128, knn);
    {
        int total = BB * 64 * KK * 259;
        group_kernel<<<(total + 255) / 256, 256>>>(x4, x3, f3, knn, grp, 64, 128, 256, total);
        launch_gemm(grp, W3, b3, hbuf, BB * 64 * KK, 259, 512, 1);
        int pt = BB * 64 * 512;
        maxpool_kernel<<<(pt + 255) / 256, 256>>>(hbuf, f4, pt, 512);
    }

    // ---- FP3: x3 <- x4 : interp f4(512) + skip f3(256), F3: 768->512 ----
    interp3_kernel<<<(BB * 128 + 127) / 128, 128>>>(x3, 128, x4, 64, f4, 512, cat, 768);
    copy_skip_kernel<<<(BB * 128 * 256 + 255) / 256, 256>>>(f3, cat, BB * 128, 256, 768, 512);
    launch_gemm(cat, F3, fb3, g3, BB * 128, 768, 512, 1);

    // ---- FP2: x2 <- x3 : interp g3(512) + skip f2(128), F2: 640->256 ----
    interp3_kernel<<<(BB * 256 + 127) / 128, 128>>>(x2, 256, x3, 128, g3, 512, cat, 640);
    copy_skip_kernel<<<(BB * 256 * 128 + 255) / 256, 256>>>(f2, cat, BB * 256, 128, 640, 512);
    launch_gemm(cat, F2, fb2, g2, BB * 256, 640, 256, 1);

    // ---- FP1: x1 <- x2 : interp g2(256) + skip f1(64), F1: 320->128 ----
    interp3_kernel<<<(BB * 512 + 127) / 128, 128>>>(x1, 512, x2, 256, g2, 256, cat, 320);
    copy_skip_kernel<<<(BB * 512 * 64 + 255) / 256, 256>>>(f1, cat, BB * 512, 64, 320, 256);
    launch_gemm(cat, F1, fb1, g1, BB * 512, 320, 128, 1);

    // ---- FP0: xyz <- x1 : interp g1(128) + skip [cls|xyz|nrm](22), F0: 150->128
    interp3_kernel<<<(BB * NN + 127) / 128, 128>>>(xyz, NN, x1, 512, g1, 128, cat, 150);
    fp0_skip_kernel<<<(BB * NN * 22 + 255) / 256, 256>>>(cls, xyz, nrm, cat);
    launch_gemm(cat, F0, fb0, g0, BB * NN, 150, 128, 1);

    // ---- seg head: g0 @ Wseg + bseg (no relu) -> out[0 : B*N*50] ----
    launch_gemm(g0, Wseg, bseg, (float*)d_out, BB * NN, 128, 50, 0);

    // ---- second output: g0 transposed [B,128,N] -> out[B*N*50 : ] ----
    const int RESULT_SZ = BB * NN * 50;
    const int G0T_SZ = BB * 128 * NN;
    if (out_size >= RESULT_SZ + G0T_SZ) {
        dim3 g(NN / 32, 128 / 32, BB);
        transpose_kernel<<<g, dim3(32, 32)>>>(g0, (float*)d_out + RESULT_SZ);
    }
}

// round 2
// speedup vs baseline: 1.3311x; 1.3311x over previous
#include <cuda_runtime.h>

// ============================================================================
// PointNet++ part-seg forward, GB300 (sm_103a). Round 2:
//  - FPS: points in SMEM, redux/ballot argmax, 2 bars/iter, FPS-first ordering
//  - kNN: register-resident top-20 (fully unrolled predicated insertion)
//  - interp3: ref tiles staged in SMEM
// ============================================================================

#define BB 8
#define NN 4096
#define KK 20

// ---- float arena offsets --------------------------------------------------
#define OFF_XYZ   0
#define SZ_PTS    (BB*NN*3)
#define OFF_NRM   (OFF_XYZ + SZ_PTS)
#define OFF_X1    (OFF_NRM + SZ_PTS)
#define OFF_X2    (OFF_X1 + BB*512*3)
#define OFF_X3    (OFF_X2 + BB*256*3)
#define OFF_X4    (OFF_X3 + BB*128*3)
#define OFF_F1    (OFF_X4 + BB*64*3)
#define OFF_F2    (OFF_F1 + BB*512*64)
#define OFF_F3    (OFF_F2 + BB*256*128)
#define OFF_F4    (OFF_F3 + BB*128*256)
#define OFF_G3    (OFF_F4 + BB*64*512)
#define OFF_G2    (OFF_G3 + BB*128*512)
#define OFF_G1    (OFF_G2 + BB*256*256)
#define OFF_G0    (OFF_G1 + BB*512*128)
#define OFF_GRP   (OFF_G0 + BB*NN*128)
#define OFF_H     (OFF_GRP + 2744320)
#define OFF_CAT   (OFF_H + 5242880)
#define ARENA_SZ  (OFF_CAT + 4915200)

__device__ float g_arena[ARENA_SZ];
__device__ int   g_iarena[BB*512*KK];   // knn idx scratch

// ---------------------------------------------------------------------------
// split x [B,6,N] -> xyz [B,N,3], nrm [B,N,3]
// ---------------------------------------------------------------------------
__global__ void split_kernel(const float* __restrict__ x,
                             float* __restrict__ xyz, float* __restrict__ nrm) {
    int i = blockIdx.x * blockDim.x + threadIdx.x;
    if (i >= BB * NN) return;
    int b = i / NN, n = i - b * NN;
    const float* base = x + (long)b * 6 * NN;
#pragma unroll
    for (int j = 0; j < 3; j++) {
        xyz[(long)i * 3 + j] = base[(long)j * NN + n];
        nrm[(long)i * 3 + j] = base[(long)(3 + j) * NN + n];
    }
}

// ---------------------------------------------------------------------------
// FPS, one block per batch. Points resident in SMEM. Matches JAX scan:
// emit far; dist=min(dist, d(.,far)); far=argmax(dist) (first-index ties).
// Source layout parameterized: coord c of point n at
//   src[b*bStride + n*pStride + c*cStride]
// Dynamic smem: 3*Npts floats (coords) + scratch (sv[32], si[32], sfar).
// ---------------------------------------------------------------------------
template<int THREADS, int PTS>
__global__ void fps_kernel(const float* __restrict__ src, long bStride,
                           int pStride, int cStride, int Npts, int S,
                           float* __restrict__ outXyz) {
    extern __shared__ float sp[];
    float* sx = sp;
    float* sy = sp + Npts;
    float* sz = sp + 2 * Npts;
    unsigned* sv = (unsigned*)(sp + 3 * Npts);
    int* si = (int*)(sv + 32);
    int* sfar = si + 32;

    const int t = threadIdx.x;
    const float* base = src + (long)blockIdx.x * bStride;
    for (int i = t; i < Npts; i += THREADS) {
        sx[i] = base[(long)i * pStride];
        sy[i] = base[(long)i * pStride + cStride];
        sz[i] = base[(long)i * pStride + 2 * cStride];
    }
    __syncthreads();

    float lx[PTS], ly[PTS], lz[PTS], dist[PTS];
    const int tbase = t * PTS;
#pragma unroll
    for (int i = 0; i < PTS; i++) {
        lx[i] = sx[tbase + i];
        ly[i] = sy[tbase + i];
        lz[i] = sz[tbase + i];
        dist[i] = 1e10f;
    }

    float* outp = outXyz + (long)blockIdx.x * S * 3;
    int far = 0;
    for (int it = 0; it < S; ++it) {
        float fx = sx[far], fy = sy[far], fz = sz[far];
        if (t == 0) {
            outp[it * 3 + 0] = fx;
            outp[it * 3 + 1] = fy;
            outp[it * 3 + 2] = fz;
        }
        float bestv = -1.0f;
        int besti = 0;
#pragma unroll
        for (int i = 0; i < PTS; i++) {
            float dx = lx[i] - fx, dy = ly[i] - fy, dz = lz[i] - fz;
            float d = fmaf(dz, dz, fmaf(dy, dy, dx * dx));
            float nd = fminf(dist[i], d);
            dist[i] = nd;
            if (nd > bestv) { bestv = nd; besti = tbase + i; }
        }
        // warp argmax: dist >= 0 so float bits compare as uint; lowest lane
        // among equals owns the smallest point index (contiguous ownership).
        unsigned bv = __float_as_uint(bestv);
        unsigned m = __reduce_max_sync(0xffffffffu, bv);
        unsigned bal = __ballot_sync(0xffffffffu, bv == m);
        int lead = __ffs((int)bal) - 1;
        int widx = __shfl_sync(0xffffffffu, besti, lead);
        if ((t & 31) == 0) { sv[t >> 5] = m; si[t >> 5] = widx; }
        __syncthreads();
        if (t < 32) {
            constexpr int NW = THREADS / 32;
            unsigned v = (t < NW) ? sv[t] : 0u;
            int idx = (t < NW) ? si[t] : 0;
            unsigned m2 = __reduce_max_sync(0xffffffffu, v);
            unsigned b2 = __ballot_sync(0xffffffffu, v == m2);
            int l2 = __ffs((int)b2) - 1;
            int f2 = __shfl_sync(0xffffffffu, idx, l2);
            if (t == 0) *sfar = f2;
        }
        __syncthreads();
        far = *sfar;
    }
}

// ---------------------------------------------------------------------------
// kNN (K=20) via expanded distance (matches ref knn()). Thread per query.
// Top-20 kept in REGISTERS: acceptance uses a fully unrolled predicated
// insertion (no dynamic indexing -> no local memory).
// ---------------------------------------------------------------------------
__global__ void knn_kernel(const float* __restrict__ q, int S,
                           const float* __restrict__ ref, int M,
                           int* __restrict__ out) {
    const int TILE = 512;
    __shared__ float sx[TILE], sy[TILE], sz[TILE], sr[TILE];
    int nqb = (S + 127) / 128;
    int b  = blockIdx.x / nqb;
    int qi = (blockIdx.x % nqb) * 128 + threadIdx.x;
    bool valid = qi < S;
    float qx = 0, qy = 0, qz = 0, qq = 0;
    if (valid) {
        const float* qp = q + ((long)b * S + qi) * 3;
        qx = qp[0]; qy = qp[1]; qz = qp[2];
        qq = qx * qx + qy * qy + qz * qz;
    }
    float bd[KK]; int bi[KK];
#pragma unroll
    for (int j = 0; j < KK; j++) { bd[j] = 3.4e38f; bi[j] = 0; }
    float worst = 3.4e38f;
    const float* rbase = ref + (long)b * M * 3;
    for (int m0 = 0; m0 < M; m0 += TILE) {
        int lim = min(TILE, M - m0);
        for (int j = threadIdx.x; j < lim; j += blockDim.x) {
            float rx = rbase[(m0 + j) * 3 + 0];
            float ry = rbase[(m0 + j) * 3 + 1];
            float rz = rbase[(m0 + j) * 3 + 2];
            sx[j] = rx; sy[j] = ry; sz[j] = rz;
            sr[j] = rx * rx + ry * ry + rz * rz;
        }
        __syncthreads();
        if (valid) {
            for (int mm = 0; mm < lim; mm++) {
                float dot = qx * sx[mm] + qy * sy[mm] + qz * sz[mm];
                float d = qq - 2.f * dot + sr[mm];
                if (d < worst) {
                    int mIdx = m0 + mm;
#pragma unroll
                    for (int j = KK - 1; j >= 1; --j) {
                        bool c1 = bd[j - 1] > d;        // whole tail shifts
                        bool c2 = bd[j] > d;            // insertion lands here
                        float nbd = c1 ? bd[j - 1] : (c2 ? d : bd[j]);
                        int   nbi = c1 ? bi[j - 1] : (c2 ? mIdx : bi[j]);
                        bd[j] = nbd; bi[j] = nbi;
                    }
                    if (bd[0] > d) { bd[0] = d; bi[0] = mIdx; }
                    worst = bd[KK - 1];
                }
            }
        }
        __syncthreads();
    }
    if (valid) {
        int* op = out + ((long)b * S + qi) * KK;
#pragma unroll
        for (int j = 0; j < KK; j++) op[j] = bi[j];
    }
}

// ---------------------------------------------------------------------------
// grouped tile: grp[b,s,k,0:3] = ref[nidx]-new ; grp[...,3:] = feats[nidx]
// ---------------------------------------------------------------------------
__global__ void group_kernel(const float* __restrict__ newxyz,
                             const float* __restrict__ refxyz,
                             const float* __restrict__ feats,
                             const int* __restrict__ knn,
                             float* __restrict__ grp,
                             int S, int M, int C, int total) {
    int Cin = C + 3;
    int stride = gridDim.x * blockDim.x;
    for (int i = blockIdx.x * blockDim.x + threadIdx.x; i < total; i += stride) {
        int c = i % Cin;
        int r = i / Cin;
        int nb = knn[r];
        int s2 = r / KK;
        int b  = s2 / S;
        float v;
        if (c < 3)
            v = refxyz[((long)b * M + nb) * 3 + c] - newxyz[(long)s2 * 3 + c];
        else
            v = feats[((long)b * M + nb) * C + (c - 3)];
        grp[i] = v;
    }
}

// ---------------------------------------------------------------------------
// Row-tiled GEMM: out[r][d] = act(sum_c A[r][c]*W[c][d] + bias[d])
// ---------------------------------------------------------------------------
__global__ void gemm_kernel(const float* __restrict__ A, const float* __restrict__ W,
                            const float* __restrict__ bias, float* __restrict__ out,
                            int rows, int Cin, int Cout, int relu) {
    extern __shared__ float sh[];
    const int RT = 16;
    int row0 = blockIdx.x * RT;
    for (int i = threadIdx.x; i < RT * Cin; i += blockDim.x) {
        int r = i / Cin, c = i - r * Cin;
        int row = row0 + r;
        sh[i] = (row < rows) ? A[(long)row * Cin + c] : 0.f;
    }
    __syncthreads();
    int d0 = (blockIdx.y * blockDim.x + threadIdx.x) * 2;
    if (d0 >= Cout) return;
    float2 acc[RT];
#pragma unroll
    for (int r = 0; r < RT; r++) acc[r] = make_float2(0.f, 0.f);
    for (int c = 0; c < Cin; c++) {
        float2 w = *reinterpret_cast<const float2*>(W + (long)c * Cout + d0);
        const float* shc = sh + c;
#pragma unroll
        for (int r = 0; r < RT; r++) {
            float v = shc[r * Cin];
            acc[r].x = fmaf(v, w.x, acc[r].x);
            acc[r].y = fmaf(v, w.y, acc[r].y);
        }
    }
    float2 bb = *reinterpret_cast<const float2*>(bias + d0);
#pragma unroll
    for (int r = 0; r < RT; r++) {
        int row = row0 + r;
        if (row < rows) {
            float vx = acc[r].x + bb.x, vy = acc[r].y + bb.y;
            if (relu) { vx = fmaxf(vx, 0.f); vy = fmaxf(vy, 0.f); }
            *reinterpret_cast<float2*>(out + (long)row * Cout + d0) = make_float2(vx, vy);
        }
    }
}

// ---------------------------------------------------------------------------
// Max-pool over K neighbors
// ---------------------------------------------------------------------------
__global__ void maxpool_kernel(const float* __restrict__ h, float* __restrict__ f,
                               int total, int C) {
    int stride = gridDim.x * blockDim.x;
    for (int i = blockIdx.x * blockDim.x + threadIdx.x; i < total; i += stride) {
        int d = i % C;
        long bs = i / C;
        const float* p = h + (bs * KK) * (long)C + d;
        float m = p[0];
#pragma unroll
        for (int k = 1; k < KK; k++) m = fmaxf(m, p[(long)k * C]);
        f[i] = m;
    }
}

// ---------------------------------------------------------------------------
// 3-NN interp: selection via expanded distance (ref knn), weights via direct
// squared diff (ref fp_block). Ref coords staged in SMEM (Mr <= 512).
// ---------------------------------------------------------------------------
__global__ void interp3_kernel(const float* __restrict__ xq, int Sq,
                               const float* __restrict__ xr, int Mr,
                               const float* __restrict__ fr, int C,
                               float* __restrict__ cat, int Ct) {
    __shared__ float rx[512], ry[512], rz[512], rr2[512];
    int nqb = (Sq + 127) / 128;
    int b  = blockIdx.x / nqb;
    int qi = (blockIdx.x % nqb) * 128 + threadIdx.x;
    const float* rp = xr + (long)b * Mr * 3;
    for (int j = threadIdx.x; j < Mr; j += blockDim.x) {
        float a = rp[j * 3 + 0], bb = rp[j * 3 + 1], cc = rp[j * 3 + 2];
        rx[j] = a; ry[j] = bb; rz[j] = cc;
        rr2[j] = a * a + bb * bb + cc * cc;
    }
    __syncthreads();
    if (qi >= Sq) return;
    const float* qp = xq + ((long)b * Sq + qi) * 3;
    float qx = qp[0], qy = qp[1], qz = qp[2];
    float qq = qx * qx + qy * qy + qz * qz;
    float bd0 = 3.4e38f, bd1 = 3.4e38f, bd2 = 3.4e38f;
    int bi0 = 0, bi1 = 0, bi2 = 0;
    for (int m = 0; m < Mr; m++) {
        float d = qq - 2.f * (qx * rx[m] + qy * ry[m] + qz * rz[m]) + rr2[m];
        if (d < bd2) {
            if (d < bd1) {
                if (d < bd0) { bd2 = bd1; bi2 = bi1; bd1 = bd0; bi1 = bi0; bd0 = d; bi0 = m; }
                else         { bd2 = bd1; bi2 = bi1; bd1 = d; bi1 = m; }
            } else           { bd2 = d; bi2 = m; }
        }
    }
    int bi[3] = { bi0, bi1, bi2 };
    float w[3]; float ws = 0.f;
#pragma unroll
    for (int j = 0; j < 3; j++) {
        float dx = rx[bi[j]] - qx, dy = ry[bi[j]] - qy, dz = rz[bi[j]] - qz;
        float dd = dx * dx + dy * dy + dz * dz;
        w[j] = 1.f / (dd + 1e-8f);
        ws += w[j];
    }
#pragma unroll
    for (int j = 0; j < 3; j++) w[j] = w[j] / ws;
    const float* f0p = fr + ((long)b * Mr + bi[0]) * C;
    const float* f1p = fr + ((long)b * Mr + bi[1]) * C;
    const float* f2p = fr + ((long)b * Mr + bi[2]) * C;
    long ro = ((long)b * Sq + qi) * Ct;
    for (int c = 0; c < C; c++)
        cat[ro + c] = w[0] * f0p[c] + w[1] * f1p[c] + w[2] * f2p[c];
}

__global__ void copy_skip_kernel(const float* __restrict__ src, float* __restrict__ cat,
                                 int rows, int Cs, int Ct, int off) {
    int total = rows * Cs;
    int stride = gridDim.x * blockDim.x;
    for (int i = blockIdx.x * blockDim.x + threadIdx.x; i < total; i += stride) {
        int row = i / Cs, c = i - row * Cs;
        cat[(long)row * Ct + off + c] = src[(long)row * Cs + c];
    }
}

__global__ void fp0_skip_kernel(const float* __restrict__ cls,
                                const float* __restrict__ xyz,
                                const float* __restrict__ nrm,
                                float* __restrict__ cat) {
    int total = BB * NN * 22;
    int stride = gridDim.x * blockDim.x;
    for (int i = blockIdx.x * blockDim.x + threadIdx.x; i < total; i += stride) {
        int c = i % 22;
        int row = i / 22;
        int b = row / NN;
        float v;
        if (c < 16)      v = cls[b * 16 + c];
        else if (c < 19) v = xyz[(long)row * 3 + (c - 16)];
        else             v = nrm[(long)row * 3 + (c - 19)];
        cat[(long)row * 150 + 128 + c] = v;
    }
}

__global__ void transpose_kernel(const float* __restrict__ in, float* __restrict__ out) {
    __shared__ float tile[32][33];
    int b = blockIdx.z;
    int n0 = blockIdx.x * 32, c0 = blockIdx.y * 32;
    int tx = threadIdx.x, ty = threadIdx.y;
    tile[ty][tx] = in[((long)b * NN + n0 + ty) * 128 + c0 + tx];
    __syncthreads();
    out[((long)b * 128 + c0 + ty) * NN + n0 + tx] = tile[tx][ty];
}

// ============================================================================
// host driver
// ============================================================================
static void launch_gemm(const float* A, const float* W, const float* bias, float* out,
                        int rows, int Cin, int Cout, int relu) {
    int bd = (Cout >= 256) ? 128 : ((Cout >= 128) ? 64 : 32);
    dim3 g((rows + 15) / 16, (Cout + bd * 2 - 1) / (bd * 2));
    gemm_kernel<<<g, bd, 16 * Cin * sizeof(float)>>>(A, W, bias, out, rows, Cin, Cout, relu);
}

static inline int fps_smem(int Npts) { return 3 * Npts * 4 + 272; }

extern "C" void kernel_launch(void* const* d_in, const int* in_sizes, int n_in,
                              void* d_out, int out_size) {
    const float* x    = (const float*)d_in[0];
    const float* cls  = (const float*)d_in[1];
    const float* W0 = (const float*)d_in[2];  const float* b0 = (const float*)d_in[3];
    const float* W1 = (const float*)d_in[4];  const float* b1 = (const float*)d_in[5];
    const float* W2 = (const float*)d_in[6];  const float* b2 = (const float*)d_in[7];
    const float* W3 = (const float*)d_in[8];  const float* b3 = (const float*)d_in[9];
    const float* F3 = (const float*)d_in[10]; const float* fb3 = (const float*)d_in[11];
    const float* F2 = (const float*)d_in[12]; const float* fb2 = (const float*)d_in[13];
    const float* F1 = (const float*)d_in[14]; const float* fb1 = (const float*)d_in[15];
    const float* F0 = (const float*)d_in[16]; const float* fb0 = (const float*)d_in[17];
    const float* Wseg = (const float*)d_in[18]; const float* bseg = (const float*)d_in[19];

    float* arena = 0; int* iar = 0;
    cudaGetSymbolAddress((void**)&arena, g_arena);
    cudaGetSymbolAddress((void**)&iar, g_iarena);

    float* xyz = arena + OFF_XYZ;
    float* nrm = arena + OFF_NRM;
    float* x1 = arena + OFF_X1; float* x2 = arena + OFF_X2;
    float* x3 = arena + OFF_X3; float* x4 = arena + OFF_X4;
    float* f1 = arena + OFF_F1; float* f2 = arena + OFF_F2;
    float* f3 = arena + OFF_F3; float* f4 = arena + OFF_F4;
    float* g3 = arena + OFF_G3; float* g2 = arena + OFF_G2;
    float* g1 = arena + OFF_G1; float* g0 = arena + OFF_G0;
    float* grp = arena + OFF_GRP;
    float* hbuf = arena + OFF_H;
    float* cat  = arena + OFF_CAT;
    int* knn  = iar;

    // Opt-in for 48KB+ dynamic smem on the stage-1 FPS instantiation.
    cudaFuncSetAttribute((const void*)fps_kernel<512, 8>,
                         cudaFuncAttributeMaxDynamicSharedMemorySize, fps_smem(NN));

    // ---- all FPS stages first (coordinate-only dependency chain) ----
    // fps1 reads x [B,6,N] directly: point n coord c at x[b*6N + c*N + n]
    fps_kernel<512, 8><<<BB, 512, fps_smem(NN)>>>(x, (long)6 * NN, 1, NN, NN, 512, x1);
    fps_kernel<256, 2><<<BB, 256, fps_smem(512)>>>(x1, 512 * 3, 3, 1, 512, 256, x2);
    fps_kernel<256, 1><<<BB, 256, fps_smem(256)>>>(x2, 256 * 3, 3, 1, 256, 128, x3);
    fps_kernel<128, 1><<<BB, 128, fps_smem(128)>>>(x3, 128 * 3, 3, 1, 128, 64, x4);

    split_kernel<<<(BB * NN + 255) / 256, 256>>>(x, xyz, nrm);

    // ---- SA1: 4096 -> 512, feats = nrm (C=3), W0: 6->64 ----
    knn_kernel<<<BB * 4, 128>>>(x1, 512, xyz, NN, knn);
    {
        int total = BB * 512 * KK * 6;
        group_kernel<<<(total + 255) / 256, 256>>>(x1, xyz, nrm, knn, grp, 512, NN, 3, total);
        launch_gemm(grp, W0, b0, hbuf, BB * 512 * KK, 6, 64, 1);
        int pt = BB * 512 * 64;
        maxpool_kernel<<<(pt + 255) / 256, 256>>>(hbuf, f1, pt, 64);
    }
    // ---- SA2: 512 -> 256, feats = f1 (C=64), W1: 67->128 ----
    knn_kernel<<<BB * 2, 128>>>(x2, 256, x1, 512, knn);
    {
        int total = BB * 256 * KK * 67;
        group_kernel<<<(total + 255) / 256, 256>>>(x2, x1, f1, knn, grp, 256, 512, 64, total);
        launch_gemm(grp, W1, b1, hbuf, BB * 256 * KK, 67, 128, 1);
        int pt = BB * 256 * 128;
        maxpool_kernel<<<(pt + 255) / 256, 256>>>(hbuf, f2, pt, 128);
    }
    // ---- SA3: 256 -> 128, feats = f2 (C=128), W2: 131->256 ----
    knn_kernel<<<BB, 128>>>(x3, 128, x2, 256, knn);
    {
        int total = BB * 128 * KK * 131;
        group_kernel<<<(total + 255) / 256, 256>>>(x3, x2, f2, knn, grp, 128, 256, 128, total);
        launch_gemm(grp, W2, b2, hbuf, BB * 128 * KK, 131, 256, 1);
        int pt = BB * 128 * 256;
        maxpool_kernel<<<(pt + 255) / 256, 256>>>(hbuf, f3, pt, 256);
    }
    // ---- SA4: 128 -> 64, feats = f3 (C=256), W3: 259->512 ----
    knn_kernel<<<BB, 128>>>(x4, 64, x3, 128, knn);
    {
        int total = BB * 64 * KK * 259;
        group_kernel<<<(total + 255) / 256, 256>>>(x4, x3, f3, knn, grp, 64, 128, 256, total);
        launch_gemm(grp, W3, b3, hbuf, BB * 64 * KK, 259, 512, 1);
        int pt = BB * 64 * 512;
        maxpool_kernel<<<(pt + 255) / 256, 256>>>(hbuf, f4, pt, 512);
    }

    // ---- FP3 ----
    interp3_kernel<<<BB, 128>>>(x3, 128, x4, 64, f4, 512, cat, 768);
    copy_skip_kernel<<<(BB * 128 * 256 + 255) / 256, 256>>>(f3, cat, BB * 128, 256, 768, 512);
    launch_gemm(cat, F3, fb3, g3, BB * 128, 768, 512, 1);

    // ---- FP2 ----
    interp3_kernel<<<BB * 2, 128>>>(x2, 256, x3, 128, g3, 512, cat, 640);
    copy_skip_kernel<<<(BB * 256 * 128 + 255) / 256, 256>>>(f2, cat, BB * 256, 128, 640, 512);
    launch_gemm(cat, F2, fb2, g2, BB * 256, 640, 256, 1);

    // ---- FP1 ----
    interp3_kernel<<<BB * 4, 128>>>(x1, 512, x2, 256, g2, 256, cat, 320);
    copy_skip_kernel<<<(BB * 512 * 64 + 255) / 256, 256>>>(f1, cat, BB * 512, 64, 320, 256);
    launch_gemm(cat, F1, fb1, g1, BB * 512, 320, 128, 1);

    // ---- FP0 ----
    interp3_kernel<<<BB * 32, 128>>>(xyz, NN, x1, 512, g1, 128, cat, 150);
    fp0_skip_kernel<<<(BB * NN * 22 + 255) / 256, 256>>>(cls, xyz, nrm, cat);
    launch_gemm(cat, F0, fb0, g0, BB * NN, 150, 128, 1);

    // ---- seg head ----
    launch_gemm(g0, Wseg, bseg, (float*)d_out, BB * NN, 128, 50, 0);

    // ---- g0 transposed ----
    const int RESULT_SZ = BB * NN * 50;
    const int G0T_SZ = BB * 128 * NN;
    if (out_size >= RESULT_SZ + G0T_SZ) {
        dim3 g(NN / 32, 128 / 32, BB);
        transpose_kernel<<<g, dim3(32, 32)>>>(g0, (float*)d_out + RESULT_SZ);
    }
}

// round 3
// speedup vs baseline: 1.4154x; 1.0634x over previous
#include <cuda_runtime.h>

// ============================================================================
// PointNet++ part-seg forward, GB300 (sm_103a). Round 3:
//  - SA blocks restructured: dense per-point projection GEMM + fused
//    gather-max (removes grouped tiles, 20x GEMM rows, maxpool)
//  - FPS: single barrier per iteration (parity double-buffered partials)
//  - kNN: float4 smem tiles + pending-candidate insert buffering
//  - interp3: two-phase with coalesced channel gather
// ============================================================================

#define BB 8
#define NN 4096
#define KK 20

// ---- float arena offsets --------------------------------------------------
#define OFF_XYZ   0
#define SZ_PTS    (BB*NN*3)
#define OFF_NRM   (OFF_XYZ + SZ_PTS)
#define OFF_X1    (OFF_NRM + SZ_PTS)
#define OFF_X2    (OFF_X1 + BB*512*3)
#define OFF_X3    (OFF_X2 + BB*256*3)
#define OFF_X4    (OFF_X3 + BB*128*3)
#define OFF_F1    (OFF_X4 + BB*64*3)
#define OFF_F2    (OFF_F1 + BB*512*64)
#define OFF_F3    (OFF_F2 + BB*256*128)
#define OFF_F4    (OFF_F3 + BB*128*256)
#define OFF_G3    (OFF_F4 + BB*64*512)
#define OFF_G2    (OFF_G3 + BB*128*512)
#define OFF_G1    (OFF_G2 + BB*256*256)
#define OFF_G0    (OFF_G1 + BB*512*128)
#define OFF_APROJ (OFF_G0 + BB*NN*128)          // max B*M*D = 8*4096*64
#define OFF_BPROJ (OFF_APROJ + 2097152)         // max B*S*D = 262144
#define OFF_IBUF  (OFF_BPROJ + 262144)          // max B*N*128 = 4194304
#define OFF_SK0   (OFF_IBUF + 4194304)          // B*N*22
#define OFF_ZERO  (OFF_SK0 + BB*NN*22)          // never written (zero-init)
#define ARENA_SZ  (OFF_ZERO + 512)

__device__ float g_arena[ARENA_SZ];
__device__ int   g_iarena[BB*512*KK];

// ---------------------------------------------------------------------------
// split x [B,6,N] -> xyz [B,N,3], nrm [B,N,3]
// ---------------------------------------------------------------------------
__global__ void split_kernel(const float* __restrict__ x,
                             float* __restrict__ xyz, float* __restrict__ nrm) {
    int i = blockIdx.x * blockDim.x + threadIdx.x;
    if (i >= BB * NN) return;
    int b = i / NN, n = i - b * NN;
    const float* base = x + (long)b * 6 * NN;
#pragma unroll
    for (int j = 0; j < 3; j++) {
        xyz[(long)i * 3 + j] = base[(long)j * NN + n];
        nrm[(long)i * 3 + j] = base[(long)(3 + j) * NN + n];
    }
}

// ---------------------------------------------------------------------------
// FPS, one block per batch. ONE barrier per iteration: per-warp partial
// argmax in parity-double-buffered shared slots; every warp redundantly
// reduces across warps (no second barrier). Tie-break = smallest index
// (lowest lane / lowest warp own ascending contiguous ranges).
// ---------------------------------------------------------------------------
template<int THREADS, int PTS>
__global__ void fps_kernel(const float* __restrict__ src, long bStride,
                           int pStride, int cStride, int Npts, int S,
                           float* __restrict__ outXyz) {
    constexpr int NW = THREADS / 32;
    extern __shared__ float sp[];
    float* sx = sp;
    float* sy = sp + Npts;
    float* sz = sp + 2 * Npts;
    __shared__ unsigned sv[2][NW];
    __shared__ int      si[2][NW];

    const int t = threadIdx.x;
    const int lane = t & 31;
    const int w = t >> 5;
    const float* base = src + (long)blockIdx.x * bStride;
    for (int i = t; i < Npts; i += THREADS) {
        sx[i] = base[(long)i * pStride];
        sy[i] = base[(long)i * pStride + cStride];
        sz[i] = base[(long)i * pStride + 2 * cStride];
    }
    __syncthreads();

    float lx[PTS], ly[PTS], lz[PTS], dist[PTS];
    const int tbase = t * PTS;
#pragma unroll
    for (int i = 0; i < PTS; i++) {
        lx[i] = sx[tbase + i];
        ly[i] = sy[tbase + i];
        lz[i] = sz[tbase + i];
        dist[i] = 1e10f;
    }

    float* outp = outXyz + (long)blockIdx.x * S * 3;
    int far = 0;
    for (int it = 0; it < S; ++it) {
        float fx = sx[far], fy = sy[far], fz = sz[far];
        if (t == 0) {
            outp[it * 3 + 0] = fx;
            outp[it * 3 + 1] = fy;
            outp[it * 3 + 2] = fz;
        }
        float bestv = -1.0f;
        int besti = 0;
#pragma unroll
        for (int i = 0; i < PTS; i++) {
            float dx = lx[i] - fx, dy = ly[i] - fy, dz = lz[i] - fz;
            float d = fmaf(dz, dz, fmaf(dy, dy, dx * dx));
            float nd = fminf(dist[i], d);
            dist[i] = nd;
            if (nd > bestv) { bestv = nd; besti = tbase + i; }
        }
        // warp argmax (dist >= 0 so float bits compare as uint)
        unsigned bv = __float_as_uint(bestv);
        unsigned m = __reduce_max_sync(0xffffffffu, bv);
        unsigned bal = __ballot_sync(0xffffffffu, bv == m);
        int lead = __ffs((int)bal) - 1;
        int widx = __shfl_sync(0xffffffffu, besti, lead);
        int p = it & 1;
        if (lane == 0) { sv[p][w] = m; si[p][w] = widx; }
        __syncthreads();
        // every warp redundantly reduces the NW partials
        unsigned v = (lane < NW) ? sv[p][lane] : 0u;
        int id = (lane < NW) ? si[p][lane] : 0;
        unsigned m2 = __reduce_max_sync(0xffffffffu, v);
        unsigned b2 = __ballot_sync(0xffffffffu, v == m2);
        int l2 = __ffs((int)b2) - 1;
        far = __shfl_sync(0xffffffffu, id, l2);
    }
}

// ---------------------------------------------------------------------------
// kNN top-20 insertion (register-resident, fully unrolled, no dyn indexing)
// ---------------------------------------------------------------------------
__device__ __forceinline__ void knn_insert(float (&bd)[KK], int (&bi)[KK],
                                           float d, int mIdx) {
#pragma unroll
    for (int j = KK - 1; j >= 1; --j) {
        bool c1 = bd[j - 1] > d;
        bool c2 = bd[j] > d;
        float nbd = c1 ? bd[j - 1] : (c2 ? d : bd[j]);
        int   nbi = c1 ? bi[j - 1] : (c2 ? mIdx : bi[j]);
        bd[j] = nbd; bi[j] = nbi;
    }
    if (bd[0] > d) { bd[0] = d; bi[0] = mIdx; }
}

// ---------------------------------------------------------------------------
// kNN (K=20), expanded distance (matches ref knn()). Thread per query,
// float4 smem ref tiles, pending-candidate buffering to amortize the
// warp-divergent insert body. All threads converged (invalid lanes compute
// junk, skip store). Final selected set identical to straight insertion.
// ---------------------------------------------------------------------------
__global__ void knn_kernel(const float* __restrict__ q, int S,
                           const float* __restrict__ ref, int M,
                           int* __restrict__ out) {
    const int TILE = 512;
    __shared__ float4 sref[TILE];
    int nqb = (S + 127) / 128;
    int b  = blockIdx.x / nqb;
    int qi = (blockIdx.x % nqb) * 128 + threadIdx.x;
    bool valid = qi < S;
    float qx = 0, qy = 0, qz = 0, qq = 0;
    if (valid) {
        const float* qp = q + ((long)b * S + qi) * 3;
        qx = qp[0]; qy = qp[1]; qz = qp[2];
        qq = qx * qx + qy * qy + qz * qz;
    }
    float bd[KK]; int bi[KK];
#pragma unroll
    for (int j = 0; j < KK; j++) { bd[j] = 3.4e38f; bi[j] = 0; }
    float worst = 3.4e38f;
    float pd = 0.f; int pi = 0; bool pend = false;
    const float* rbase = ref + (long)b * M * 3;
    for (int m0 = 0; m0 < M; m0 += TILE) {
        int lim = min(TILE, M - m0);
        for (int j = threadIdx.x; j < lim; j += blockDim.x) {
            float rx = rbase[(m0 + j) * 3 + 0];
            float ry = rbase[(m0 + j) * 3 + 1];
            float rz = rbase[(m0 + j) * 3 + 2];
            sref[j] = make_float4(rx, ry, rz, rx * rx + ry * ry + rz * rz);
        }
        __syncthreads();
        for (int mm = 0; mm < lim; mm++) {
            float4 r = sref[mm];
            float dot = qx * r.x + qy * r.y + qz * r.z;
            float d = qq - 2.f * dot + r.w;
            bool acc = d < worst;
            bool must = acc && pend;
            if (__any_sync(0xffffffffu, must)) {
                if (pend) {
                    knn_insert(bd, bi, pd, pi);
                    pend = false;
                    worst = bd[KK - 1];
                }
            }
            if (acc) { pd = d; pi = m0 + mm; pend = true; }
        }
        __syncthreads();
    }
    if (pend) { knn_insert(bd, bi, pd, pi); }
    if (valid) {
        int* op = out + ((long)b * S + qi) * KK;
#pragma unroll
        for (int j = 0; j < KK; j++) op[j] = bi[j];
    }
}

// ---------------------------------------------------------------------------
// GEMM over [A1 | A2] concat inputs: out[r][d] = act(sum_c in[r][c]*W[c][d]+b)
// A1 width C1, A2 width C2 (A2 may be null, C2=0). bias may be null (=0).
// 16-row tiles in shared; each thread computes 2 output channels.
// ---------------------------------------------------------------------------
__global__ void gemm2_kernel(const float* __restrict__ A1, int C1,
                             const float* __restrict__ A2, int C2,
                             const float* __restrict__ W,
                             const float* __restrict__ bias,
                             float* __restrict__ out,
                             int rows, int Cout, int relu) {
    extern __shared__ float sh[];
    const int RT = 16;
    const int Cin = C1 + C2;
    int row0 = blockIdx.x * RT;
    for (int i = threadIdx.x; i < RT * Cin; i += blockDim.x) {
        int r = i / Cin, c = i - r * Cin;
        int row = row0 + r;
        float v = 0.f;
        if (row < rows) {
            if (c < C1) v = A1[(long)row * C1 + c];
            else        v = A2[(long)row * C2 + (c - C1)];
        }
        sh[i] = v;
    }
    __syncthreads();
    int d0 = (blockIdx.y * blockDim.x + threadIdx.x) * 2;
    if (d0 >= Cout) return;
    float2 acc[RT];
#pragma unroll
    for (int r = 0; r < RT; r++) acc[r] = make_float2(0.f, 0.f);
    for (int c = 0; c < Cin; c++) {
        float2 w = *reinterpret_cast<const float2*>(W + (long)c * Cout + d0);
        const float* shc = sh + c;
#pragma unroll
        for (int r = 0; r < RT; r++) {
            float v = shc[r * Cin];
            acc[r].x = fmaf(v, w.x, acc[r].x);
            acc[r].y = fmaf(v, w.y, acc[r].y);
        }
    }
    float2 bb = bias ? *reinterpret_cast<const float2*>(bias + d0)
                     : make_float2(0.f, 0.f);
#pragma unroll
    for (int r = 0; r < RT; r++) {
        int row = row0 + r;
        if (row < rows) {
            float vx = acc[r].x + bb.x, vy = acc[r].y + bb.y;
            if (relu) { vx = fmaxf(vx, 0.f); vy = fmaxf(vy, 0.f); }
            *reinterpret_cast<float2*>(out + (long)row * Cout + d0) = make_float2(vx, vy);
        }
    }
}

// ---------------------------------------------------------------------------
// Fused gather-max for SA blocks:
// f[b,s,d] = relu( max_k A[b, nidx[b,s,k], d] - Bp[b,s,d] )
// One block per (b,s); threads over d (coalesced A rows).
// ---------------------------------------------------------------------------
__global__ void gathermax_kernel(const float* __restrict__ A,
                                 const float* __restrict__ Bp,
                                 const int* __restrict__ nidx,
                                 float* __restrict__ f,
                                 int S, int M, int D) {
    __shared__ int idx[KK];
    int bs = blockIdx.x;            // b*S + s
    int b = bs / S;
    if (threadIdx.x < KK) idx[threadIdx.x] = nidx[(long)bs * KK + threadIdx.x];
    __syncthreads();
    const float* Abase = A + (long)b * M * D;
    for (int d = threadIdx.x; d < D; d += blockDim.x) {
        float m = -3.4e38f;
#pragma unroll 4
        for (int k = 0; k < KK; k++)
            m = fmaxf(m, Abase[(long)idx[k] * D + d]);
        f[(long)bs * D + d] = fmaxf(m - Bp[(long)bs * D + d], 0.f);
    }
}

// ---------------------------------------------------------------------------
// 3-NN interp, two-phase. Phase A: thread-per-query 3NN (expanded distance
// selection, direct-diff weights — matches ref). Phase B: block-cooperative
// coalesced channel gather. Requires Sq % 128 == 0 (holds: 128..4096).
// ---------------------------------------------------------------------------
__global__ void interp3_kernel(const float* __restrict__ xq, int Sq,
                               const float* __restrict__ xr, int Mr,
                               const float* __restrict__ fr, int C,
                               float* __restrict__ out) {
    __shared__ float rx[512], ry[512], rz[512], rr2[512];
    __shared__ float qw[128][3];
    __shared__ int   qb[128][3];
    int nqb = Sq / 128;
    int b  = blockIdx.x / nqb;
    int q0 = (blockIdx.x % nqb) * 128;
    const float* rp = xr + (long)b * Mr * 3;
    for (int j = threadIdx.x; j < Mr; j += blockDim.x) {
        float a = rp[j * 3 + 0], bb = rp[j * 3 + 1], cc = rp[j * 3 + 2];
        rx[j] = a; ry[j] = bb; rz[j] = cc;
        rr2[j] = a * a + bb * bb + cc * cc;
    }
    __syncthreads();
    {
        int qi = q0 + threadIdx.x;
        const float* qp = xq + ((long)b * Sq + qi) * 3;
        float qx = qp[0], qy = qp[1], qz = qp[2];
        float qq = qx * qx + qy * qy + qz * qz;
        float bd0 = 3.4e38f, bd1 = 3.4e38f, bd2 = 3.4e38f;
        int bi0 = 0, bi1 = 0, bi2 = 0;
        for (int m = 0; m < Mr; m++) {
            float d = qq - 2.f * (qx * rx[m] + qy * ry[m] + qz * rz[m]) + rr2[m];
            if (d < bd2) {
                if (d < bd1) {
                    if (d < bd0) { bd2 = bd1; bi2 = bi1; bd1 = bd0; bi1 = bi0; bd0 = d; bi0 = m; }
                    else         { bd2 = bd1; bi2 = bi1; bd1 = d; bi1 = m; }
                } else           { bd2 = d; bi2 = m; }
            }
        }
        int bis[3] = { bi0, bi1, bi2 };
        float w[3]; float ws = 0.f;
#pragma unroll
        for (int j = 0; j < 3; j++) {
            float dx = rx[bis[j]] - qx, dy = ry[bis[j]] - qy, dz = rz[bis[j]] - qz;
            float dd = dx * dx + dy * dy + dz * dz;
            w[j] = 1.f / (dd + 1e-8f);
            ws += w[j];
        }
#pragma unroll
        for (int j = 0; j < 3; j++) {
            qw[threadIdx.x][j] = w[j] / ws;
            qb[threadIdx.x][j] = bis[j];
        }
    }
    __syncthreads();
    // Phase B: coalesced gather of fr rows
    for (int qv = 0; qv < 128; ++qv) {
        float w0 = qw[qv][0], w1 = qw[qv][1], w2 = qw[qv][2];
        const float* f0 = fr + ((long)b * Mr + qb[qv][0]) * C;
        const float* f1 = fr + ((long)b * Mr + qb[qv][1]) * C;
        const float* f2 = fr + ((long)b * Mr + qb[qv][2]) * C;
        long ro = ((long)b * Sq + q0 + qv) * C;
        for (int c = threadIdx.x; c < C; c += blockDim.x)
            out[ro + c] = w0 * f0[c] + w1 * f1[c] + w2 * f2[c];
    }
}

// FP0 skip: [cls(16) | xyz(3) | nrm(3)] compact width-22 rows
__global__ void fp0_skip_kernel(const float* __restrict__ cls,
                                const float* __restrict__ xyz,
                                const float* __restrict__ nrm,
                                float* __restrict__ sk) {
    int total = BB * NN * 22;
    int stride = gridDim.x * blockDim.x;
    for (int i = blockIdx.x * blockDim.x + threadIdx.x; i < total; i += stride) {
        int c = i % 22;
        int row = i / 22;
        int b = row / NN;
        float v;
        if (c < 16)      v = cls[b * 16 + c];
        else if (c < 19) v = xyz[(long)row * 3 + (c - 16)];
        else             v = nrm[(long)row * 3 + (c - 19)];
        sk[i] = v;
    }
}

// g0 [B,N,128] -> out [B,128,N]
__global__ void transpose_kernel(const float* __restrict__ in, float* __restrict__ out) {
    __shared__ float tile[32][33];
    int b = blockIdx.z;
    int n0 = blockIdx.x * 32, c0 = blockIdx.y * 32;
    int tx = threadIdx.x, ty = threadIdx.y;
    tile[ty][tx] = in[((long)b * NN + n0 + ty) * 128 + c0 + tx];
    __syncthreads();
    out[((long)b * 128 + c0 + ty) * NN + n0 + tx] = tile[tx][ty];
}

// ============================================================================
// host driver
// ============================================================================
static void launch_gemm2(const float* A1, int C1, const float* A2, int C2,
                         const float* W, const float* bias, float* out,
                         int rows, int Cout, int relu) {
    int bd = (Cout >= 256) ? 128 : ((Cout >= 128) ? 64 : 32);
    dim3 g((rows + 15) / 16, (Cout + bd * 2 - 1) / (bd * 2));
    gemm2_kernel<<<g, bd, 16 * (C1 + C2) * sizeof(float)>>>(
        A1, C1, A2, C2, W, bias, out, rows, Cout, relu);
}

extern "C" void kernel_launch(void* const* d_in, const int* in_sizes, int n_in,
                              void* d_out, int out_size) {
    const float* x    = (const float*)d_in[0];
    const float* cls  = (const float*)d_in[1];
    const float* W0 = (const float*)d_in[2];  const float* b0 = (const float*)d_in[3];
    const float* W1 = (const float*)d_in[4];  const float* b1 = (const float*)d_in[5];
    const float* W2 = (const float*)d_in[6];  const float* b2 = (const float*)d_in[7];
    const float* W3 = (const float*)d_in[8];  const float* b3 = (const float*)d_in[9];
    const float* F3 = (const float*)d_in[10]; const float* fb3 = (const float*)d_in[11];
    const float* F2 = (const float*)d_in[12]; const float* fb2 = (const float*)d_in[13];
    const float* F1 = (const float*)d_in[14]; const float* fb1 = (const float*)d_in[15];
    const float* F0 = (const float*)d_in[16]; const float* fb0 = (const float*)d_in[17];
    const float* Wseg = (const float*)d_in[18]; const float* bseg = (const float*)d_in[19];

    float* arena = 0; int* iar = 0;
    cudaGetSymbolAddress((void**)&arena, g_arena);
    cudaGetSymbolAddress((void**)&iar, g_iarena);

    float* xyz = arena + OFF_XYZ;
    float* nrm = arena + OFF_NRM;
    float* x1 = arena + OFF_X1; float* x2 = arena + OFF_X2;
    float* x3 = arena + OFF_X3; float* x4 = arena + OFF_X4;
    float* f1 = arena + OFF_F1; float* f2 = arena + OFF_F2;
    float* f3 = arena + OFF_F3; float* f4 = arena + OFF_F4;
    float* g3 = arena + OFF_G3; float* g2 = arena + OFF_G2;
    float* g1 = arena + OFF_G1; float* g0 = arena + OFF_G0;
    float* aproj = arena + OFF_APROJ;
    float* bproj = arena + OFF_BPROJ;
    float* ibuf  = arena + OFF_IBUF;
    float* sk0   = arena + OFF_SK0;
    int* knn = iar;

    cudaFuncSetAttribute((const void*)fps_kernel<512, 8>,
                         cudaFuncAttributeMaxDynamicSharedMemorySize, 3 * NN * 4);

    // ---- FPS chain (coordinate-only deps) ----
    fps_kernel<512, 8><<<BB, 512, 3 * NN * 4>>>(x, (long)6 * NN, 1, NN, NN, 512, x1);
    fps_kernel<256, 2><<<BB, 256, 3 * 512 * 4>>>(x1, 512 * 3, 3, 1, 512, 256, x2);
    fps_kernel<256, 1><<<BB, 256, 3 * 256 * 4>>>(x2, 256 * 3, 3, 1, 256, 128, x3);
    fps_kernel<128, 1><<<BB, 128, 3 * 128 * 4>>>(x3, 128 * 3, 3, 1, 128, 64, x4);

    split_kernel<<<(BB * NN + 255) / 256, 256>>>(x, xyz, nrm);

    // ---- SA1: 4096 -> 512, feats=nrm(3), W0: 6->64 ----
    knn_kernel<<<BB * 4, 128>>>(x1, 512, xyz, NN, knn);
    launch_gemm2(xyz, 3, nrm, 3, W0, b0, aproj, BB * NN, 64, 0);
    launch_gemm2(x1, 3, 0, 0, W0, 0, bproj, BB * 512, 64, 0);
    gathermax_kernel<<<BB * 512, 64>>>(aproj, bproj, knn, f1, 512, NN, 64);

    // ---- SA2: 512 -> 256, feats=f1(64), W1: 67->128 ----
    knn_kernel<<<BB * 2, 128>>>(x2, 256, x1, 512, knn);
    launch_gemm2(x1, 3, f1, 64, W1, b1, aproj, BB * 512, 128, 0);
    launch_gemm2(x2, 3, 0, 0, W1, 0, bproj, BB * 256, 128, 0);
    gathermax_kernel<<<BB * 256, 128>>>(aproj, bproj, knn, f2, 256, 512, 128);

    // ---- SA3: 256 -> 128, feats=f2(128), W2: 131->256 ----
    knn_kernel<<<BB, 128>>>(x3, 128, x2, 256, knn);
    launch_gemm2(x2, 3, f2, 128, W2, b2, aproj, BB * 256, 256, 0);
    launch_gemm2(x3, 3, 0, 0, W2, 0, bproj, BB * 128, 256, 0);
    gathermax_kernel<<<BB * 128, 128>>>(aproj, bproj, knn, f3, 128, 256, 256);

    // ---- SA4: 128 -> 64, feats=f3(256), W3: 259->512 ----
    knn_kernel<<<BB, 128>>>(x4, 64, x3, 128, knn);
    launch_gemm2(x3, 3, f3, 256, W3, b3, aproj, BB * 128, 512, 0);
    launch_gemm2(x4, 3, 0, 0, W3, 0, bproj, BB * 64, 512, 0);
    gathermax_kernel<<<BB * 64, 128>>>(aproj, bproj, knn, f4, 64, 128, 512);

    // ---- FP3: x3 <- x4 : interp f4(512) + skip f3(256), F3: 768->512 ----
    interp3_kernel<<<BB, 128>>>(x3, 128, x4, 64, f4, 512, ibuf);
    launch_gemm2(ibuf, 512, f3, 256, F3, fb3, g3, BB * 128, 512, 1);

    // ---- FP2: x2 <- x3 : interp g3(512) + skip f2(128), F2: 640->256 ----
    interp3_kernel<<<BB * 2, 128>>>(x2, 256, x3, 128, g3, 512, ibuf);
    launch_gemm2(ibuf, 512, f2, 128, F2, fb2, g2, BB * 256, 256, 1);

    // ---- FP1: x1 <- x2 : interp g2(256) + skip f1(64), F1: 320->128 ----
    interp3_kernel<<<BB * 4, 128>>>(x1, 512, x2, 256, g2, 256, ibuf);
    launch_gemm2(ibuf, 256, f1, 64, F1, fb1, g1, BB * 512, 128, 1);

    // ---- FP0: xyz <- x1 : interp g1(128) + skip [cls|xyz|nrm](22), F0 ----
    interp3_kernel<<<BB * 32, 128>>>(xyz, NN, x1, 512, g1, 128, ibuf);
    fp0_skip_kernel<<<(BB * NN * 22 + 255) / 256, 256>>>(cls, xyz, nrm, sk0);
    launch_gemm2(ibuf, 128, sk0, 22, F0, fb0, g0, BB * NN, 128, 1);

    // ---- seg head ----
    launch_gemm2(g0, 128, 0, 0, Wseg, bseg, (float*)d_out, BB * NN, 50, 0);

    // ---- g0 transposed ----
    const int RESULT_SZ = BB * NN * 50;
    const int G0T_SZ = BB * 128 * NN;
    if (out_size >= RESULT_SZ + G0T_SZ) {
        dim3 g(NN / 32, 128 / 32, BB);
        transpose_kernel<<<g, dim3(32, 32)>>>(g0, (float*)d_out + RESULT_SZ);
    }
}

// round 6
// speedup vs baseline: 1.6448x; 1.1621x over previous
#include <cuda_runtime.h>

// ============================================================================
// PointNet++ part-seg forward, GB300 (sm_103a). Round 4 (resubmitted after
// infra failure):
//  - GEMMs: packed fma.rn.f32x2 (2x fp32 FMA tput), pre-packed smem broadcast,
//    4 output cols/thread, adaptive row tile (>=256 blocks per launch)
//  - FPS: per-stage thread shaping (stage4 single-warp, no barriers)
//  - launch order puts fps1 at profiled slot #4
// ============================================================================

#define BB 8
#define NN 4096
#define KK 20

typedef unsigned long long ull;

// ---- float arena offsets --------------------------------------------------
#define OFF_XYZ   0
#define SZ_PTS    (BB*NN*3)
#define OFF_NRM   (OFF_XYZ + SZ_PTS)
#define OFF_X1    (OFF_NRM + SZ_PTS)
#define OFF_X2    (OFF_X1 + BB*512*3)
#define OFF_X3    (OFF_X2 + BB*256*3)
#define OFF_X4    (OFF_X3 + BB*128*3)
#define OFF_F1    (OFF_X4 + BB*64*3)
#define OFF_F2    (OFF_F1 + BB*512*64)
#define OFF_F3    (OFF_F2 + BB*256*128)
#define OFF_F4    (OFF_F3 + BB*128*256)
#define OFF_G3    (OFF_F4 + BB*64*512)
#define OFF_G2    (OFF_G3 + BB*128*512)
#define OFF_G1    (OFF_G2 + BB*256*256)
#define OFF_G0    (OFF_G1 + BB*512*128)
#define OFF_APROJ (OFF_G0 + BB*NN*128)          // max B*M*D = 8*4096*64
#define OFF_BPROJ (OFF_APROJ + 2097152)
#define OFF_IBUF  (OFF_BPROJ + 262144)          // max B*N*128
#define OFF_SK0   (OFF_IBUF + 4194304)
#define ARENA_SZ  (OFF_SK0 + BB*NN*22 + 512)

__device__ float g_arena[ARENA_SZ];
__device__ int   g_iarena[BB*512*KK];

// ---- packed f32x2 helpers --------------------------------------------------
__device__ __forceinline__ ull pack2s(float v) {
    ull r; unsigned u = __float_as_uint(v);
    asm("mov.b64 %0, {%1, %1};" : "=l"(r) : "r"(u));
    return r;
}
__device__ __forceinline__ ull fma2(ull a, ull b, ull c) {
    ull d; asm("fma.rn.f32x2 %0, %1, %2, %3;" : "=l"(d) : "l"(a), "l"(b), "l"(c));
    return d;
}
__device__ __forceinline__ float2 unpack2(ull v) {
    unsigned lo, hi;
    asm("mov.b64 {%0, %1}, %2;" : "=r"(lo), "=r"(hi) : "l"(v));
    return make_float2(__uint_as_float(lo), __uint_as_float(hi));
}

// ---------------------------------------------------------------------------
// split x [B,6,N] -> xyz [B,N,3], nrm [B,N,3]
// ---------------------------------------------------------------------------
__global__ void split_kernel(const float* __restrict__ x,
                             float* __restrict__ xyz, float* __restrict__ nrm) {
    int i = blockIdx.x * blockDim.x + threadIdx.x;
    if (i >= BB * NN) return;
    int b = i / NN, n = i - b * NN;
    const float* base = x + (long)b * 6 * NN;
#pragma unroll
    for (int j = 0; j < 3; j++) {
        xyz[(long)i * 3 + j] = base[(long)j * NN + n];
        nrm[(long)i * 3 + j] = base[(long)(3 + j) * NN + n];
    }
}

// ---------------------------------------------------------------------------
// FPS. One block per batch. Matches JAX scan exactly (first-index ties).
// THREADS==32 specialization: no barriers, no cross-warp phase.
// ---------------------------------------------------------------------------
template<int THREADS, int PTS>
__global__ void fps_kernel(const float* __restrict__ src, long bStride,
                           int pStride, int cStride, int Npts, int S,
                           float* __restrict__ outXyz) {
    constexpr int NW = THREADS / 32;
    extern __shared__ float sp[];
    float* sx = sp;
    float* sy = sp + Npts;
    float* sz = sp + 2 * Npts;
    __shared__ unsigned sv[2][NW > 1 ? NW : 1];
    __shared__ int      si[2][NW > 1 ? NW : 1];

    const int t = threadIdx.x;
    const int lane = t & 31;
    const int w = t >> 5;
    const float* base = src + (long)blockIdx.x * bStride;
    for (int i = t; i < Npts; i += THREADS) {
        sx[i] = base[(long)i * pStride];
        sy[i] = base[(long)i * pStride + cStride];
        sz[i] = base[(long)i * pStride + 2 * cStride];
    }
    __syncthreads();

    float lx[PTS], ly[PTS], lz[PTS], dist[PTS];
    const int tbase = t * PTS;
#pragma unroll
    for (int i = 0; i < PTS; i++) {
        lx[i] = sx[tbase + i];
        ly[i] = sy[tbase + i];
        lz[i] = sz[tbase + i];
        dist[i] = 1e10f;
    }

    float* outp = outXyz + (long)blockIdx.x * S * 3;
    int far = 0;
    for (int it = 0; it < S; ++it) {
        float fx = sx[far], fy = sy[far], fz = sz[far];
        if (t == 0) {
            outp[it * 3 + 0] = fx;
            outp[it * 3 + 1] = fy;
            outp[it * 3 + 2] = fz;
        }
        float bestv = -1.0f;
        int besti = 0;
#pragma unroll
        for (int i = 0; i < PTS; i++) {
            float dx = lx[i] - fx, dy = ly[i] - fy, dz = lz[i] - fz;
            float d = fmaf(dz, dz, fmaf(dy, dy, dx * dx));
            float nd = fminf(dist[i], d);
            dist[i] = nd;
            if (nd > bestv) { bestv = nd; besti = tbase + i; }
        }
        unsigned bv = __float_as_uint(bestv);
        unsigned m = __reduce_max_sync(0xffffffffu, bv);
        unsigned bal = __ballot_sync(0xffffffffu, bv == m);
        int lead = __ffs((int)bal) - 1;
        int widx = __shfl_sync(0xffffffffu, besti, lead);
        if (THREADS == 32) {
            far = widx;
        } else {
            int p = it & 1;
            if (lane == 0) { sv[p][w] = m; si[p][w] = widx; }
            __syncthreads();
            unsigned v = (lane < NW) ? sv[p][lane] : 0u;
            int id = (lane < NW) ? si[p][lane] : 0;
            unsigned m2 = __reduce_max_sync(0xffffffffu, v);
            unsigned b2 = __ballot_sync(0xffffffffu, v == m2);
            int l2 = __ffs((int)b2) - 1;
            far = __shfl_sync(0xffffffffu, id, l2);
        }
    }
}

// ---------------------------------------------------------------------------
// kNN (K=20), expanded distance (matches ref). Register top-20, pending-
// candidate buffering of the warp-divergent insert.
// ---------------------------------------------------------------------------
__device__ __forceinline__ void knn_insert(float (&bd)[KK], int (&bi)[KK],
                                           float d, int mIdx) {
#pragma unroll
    for (int j = KK - 1; j >= 1; --j) {
        bool c1 = bd[j - 1] > d;
        bool c2 = bd[j] > d;
        float nbd = c1 ? bd[j - 1] : (c2 ? d : bd[j]);
        int   nbi = c1 ? bi[j - 1] : (c2 ? mIdx : bi[j]);
        bd[j] = nbd; bi[j] = nbi;
    }
    if (bd[0] > d) { bd[0] = d; bi[0] = mIdx; }
}

__global__ void knn_kernel(const float* __restrict__ q, int S,
                           const float* __restrict__ ref, int M,
                           int* __restrict__ out) {
    const int TILE = 512;
    __shared__ float4 sref[TILE];
    int nqb = (S + 127) / 128;
    int b  = blockIdx.x / nqb;
    int qi = (blockIdx.x % nqb) * 128 + threadIdx.x;
    bool valid = qi < S;
    float qx = 0, qy = 0, qz = 0, qq = 0;
    if (valid) {
        const float* qp = q + ((long)b * S + qi) * 3;
        qx = qp[0]; qy = qp[1]; qz = qp[2];
        qq = qx * qx + qy * qy + qz * qz;
    }
    float bd[KK]; int bi[KK];
#pragma unroll
    for (int j = 0; j < KK; j++) { bd[j] = 3.4e38f; bi[j] = 0; }
    float worst = 3.4e38f;
    float pd = 0.f; int pi = 0; bool pend = false;
    const float* rbase = ref + (long)b * M * 3;
    for (int m0 = 0; m0 < M; m0 += TILE) {
        int lim = min(TILE, M - m0);
        for (int j = threadIdx.x; j < lim; j += blockDim.x) {
            float rx = rbase[(m0 + j) * 3 + 0];
            float ry = rbase[(m0 + j) * 3 + 1];
            float rz = rbase[(m0 + j) * 3 + 2];
            sref[j] = make_float4(rx, ry, rz, rx * rx + ry * ry + rz * rz);
        }
        __syncthreads();
        for (int mm = 0; mm < lim; mm++) {
            float4 r = sref[mm];
            float dot = qx * r.x + qy * r.y + qz * r.z;
            float d = qq - 2.f * dot + r.w;
            bool acc = d < worst;
            bool must = acc && pend;
            if (__any_sync(0xffffffffu, must)) {
                if (pend) {
                    knn_insert(bd, bi, pd, pi);
                    pend = false;
                    worst = bd[KK - 1];
                }
            }
            if (acc) { pd = d; pi = m0 + mm; pend = true; }
        }
        __syncthreads();
    }
    if (pend) { knn_insert(bd, bi, pd, pi); }
    if (valid) {
        int* op = out + ((long)b * S + qi) * KK;
#pragma unroll
        for (int j = 0; j < KK; j++) op[j] = bi[j];
    }
}

// ---------------------------------------------------------------------------
// GEMM4: out[r][d] = act(sum_c [A1|A2][r][c]*W[c][d] + bias[d]),
// 4 output cols/thread via two fma.rn.f32x2; smem holds (v,v)-packed rows.
// Requires Cout % 4 == 0.
// ---------------------------------------------------------------------------
template<int RT>
__global__ void gemm4_kernel(const float* __restrict__ A1, int C1,
                             const float* __restrict__ A2, int C2,
                             const float* __restrict__ W,
                             const float* __restrict__ bias,
                             float* __restrict__ out,
                             int rows, int Cout, int relu) {
    extern __shared__ ull shu[];
    const int Cin = C1 + C2;
    int row0 = blockIdx.x * RT;
    for (int i = threadIdx.x; i < RT * Cin; i += blockDim.x) {
        int r = i / Cin, c = i - r * Cin;
        int row = row0 + r;
        float v = 0.f;
        if (row < rows) {
            if (c < C1) v = A1[(long)row * C1 + c];
            else        v = A2[(long)row * C2 + (c - C1)];
        }
        shu[i] = pack2s(v);
    }
    __syncthreads();
    int d0 = (blockIdx.y * blockDim.x + threadIdx.x) * 4;
    if (d0 >= Cout) return;
    ull acc0[RT], acc1[RT];
#pragma unroll
    for (int r = 0; r < RT; r++) { acc0[r] = 0ull; acc1[r] = 0ull; }
    for (int c = 0; c < Cin; c++) {
        ulonglong2 wv = *reinterpret_cast<const ulonglong2*>(W + (long)c * Cout + d0);
        const ull* shc = shu + c;
#pragma unroll
        for (int r = 0; r < RT; r++) {
            ull vv = shc[r * Cin];
            acc0[r] = fma2(vv, wv.x, acc0[r]);
            acc1[r] = fma2(vv, wv.y, acc1[r]);
        }
    }
    float4 bb = bias ? *reinterpret_cast<const float4*>(bias + d0)
                     : make_float4(0.f, 0.f, 0.f, 0.f);
#pragma unroll
    for (int r = 0; r < RT; r++) {
        int row = row0 + r;
        if (row < rows) {
            float2 p0 = unpack2(acc0[r]);
            float2 p1 = unpack2(acc1[r]);
            float v0 = p0.x + bb.x, v1 = p0.y + bb.y;
            float v2 = p1.x + bb.z, v3 = p1.y + bb.w;
            if (relu) {
                v0 = fmaxf(v0, 0.f); v1 = fmaxf(v1, 0.f);
                v2 = fmaxf(v2, 0.f); v3 = fmaxf(v3, 0.f);
            }
            *reinterpret_cast<float4*>(out + (long)row * Cout + d0) =
                make_float4(v0, v1, v2, v3);
        }
    }
}

// 2-col GEMM kept for Cout=50 (seg head)
__global__ void gemm2_kernel(const float* __restrict__ A1, int C1,
                             const float* __restrict__ W,
                             const float* __restrict__ bias,
                             float* __restrict__ out,
                             int rows, int Cout, int relu) {
    extern __shared__ float sh[];
    const int RT = 16;
    const int Cin = C1;
    int row0 = blockIdx.x * RT;
    for (int i = threadIdx.x; i < RT * Cin; i += blockDim.x) {
        int r = i / Cin, c = i - r * Cin;
        int row = row0 + r;
        sh[i] = (row < rows) ? A1[(long)row * C1 + c] : 0.f;
    }
    __syncthreads();
    int d0 = (blockIdx.y * blockDim.x + threadIdx.x) * 2;
    if (d0 >= Cout) return;
    float2 acc[RT];
#pragma unroll
    for (int r = 0; r < RT; r++) acc[r] = make_float2(0.f, 0.f);
    for (int c = 0; c < Cin; c++) {
        float2 w = *reinterpret_cast<const float2*>(W + (long)c * Cout + d0);
        const float* shc = sh + c;
#pragma unroll
        for (int r = 0; r < RT; r++) {
            float v = shc[r * Cin];
            acc[r].x = fmaf(v, w.x, acc[r].x);
            acc[r].y = fmaf(v, w.y, acc[r].y);
        }
    }
    float2 bb = bias ? *reinterpret_cast<const float2*>(bias + d0)
                     : make_float2(0.f, 0.f);
#pragma unroll
    for (int r = 0; r < RT; r++) {
        int row = row0 + r;
        if (row < rows) {
            float vx = acc[r].x + bb.x, vy = acc[r].y + bb.y;
            if (relu) { vx = fmaxf(vx, 0.f); vy = fmaxf(vy, 0.f); }
            *reinterpret_cast<float2*>(out + (long)row * Cout + d0) = make_float2(vx, vy);
        }
    }
}

// ---------------------------------------------------------------------------
// Fused gather-max: f[b,s,d] = relu( max_k A[b,nidx[b,s,k],d] - Bp[b,s,d] )
// ---------------------------------------------------------------------------
__global__ void gathermax_kernel(const float* __restrict__ A,
                                 const float* __restrict__ Bp,
                                 const int* __restrict__ nidx,
                                 float* __restrict__ f,
                                 int S, int M, int D) {
    __shared__ int idx[KK];
    int bs = blockIdx.x;
    int b = bs / S;
    if (threadIdx.x < KK) idx[threadIdx.x] = nidx[(long)bs * KK + threadIdx.x];
    __syncthreads();
    const float* Abase = A + (long)b * M * D;
    for (int d = threadIdx.x; d < D; d += blockDim.x) {
        float m = -3.4e38f;
#pragma unroll 4
        for (int k = 0; k < KK; k++)
            m = fmaxf(m, Abase[(long)idx[k] * D + d]);
        f[(long)bs * D + d] = fmaxf(m - Bp[(long)bs * D + d], 0.f);
    }
}

// ---------------------------------------------------------------------------
// 3-NN interp, two-phase (selection matches ref knn; weights ref fp_block).
// ---------------------------------------------------------------------------
__global__ void interp3_kernel(const float* __restrict__ xq, int Sq,
                               const float* __restrict__ xr, int Mr,
                               const float* __restrict__ fr, int C,
                               float* __restrict__ out) {
    __shared__ float rx[512], ry[512], rz[512], rr2[512];
    __shared__ float qw[128][3];
    __shared__ int   qb[128][3];
    int nqb = Sq / 128;
    int b  = blockIdx.x / nqb;
    int q0 = (blockIdx.x % nqb) * 128;
    const float* rp = xr + (long)b * Mr * 3;
    for (int j = threadIdx.x; j < Mr; j += blockDim.x) {
        float a = rp[j * 3 + 0], bb = rp[j * 3 + 1], cc = rp[j * 3 + 2];
        rx[j] = a; ry[j] = bb; rz[j] = cc;
        rr2[j] = a * a + bb * bb + cc * cc;
    }
    __syncthreads();
    {
        int qi = q0 + threadIdx.x;
        const float* qp = xq + ((long)b * Sq + qi) * 3;
        float qx = qp[0], qy = qp[1], qz = qp[2];
        float qq = qx * qx + qy * qy + qz * qz;
        float bd0 = 3.4e38f, bd1 = 3.4e38f, bd2 = 3.4e38f;
        int bi0 = 0, bi1 = 0, bi2 = 0;
        for (int m = 0; m < Mr; m++) {
            float d = qq - 2.f * (qx * rx[m] + qy * ry[m] + qz * rz[m]) + rr2[m];
            if (d < bd2) {
                if (d < bd1) {
                    if (d < bd0) { bd2 = bd1; bi2 = bi1; bd1 = bd0; bi1 = bi0; bd0 = d; bi0 = m; }
                    else         { bd2 = bd1; bi2 = bi1; bd1 = d; bi1 = m; }
                } else           { bd2 = d; bi2 = m; }
            }
        }
        int bis[3] = { bi0, bi1, bi2 };
        float w[3]; float ws = 0.f;
#pragma unroll
        for (int j = 0; j < 3; j++) {
            float dx = rx[bis[j]] - qx, dy = ry[bis[j]] - qy, dz = rz[bis[j]] - qz;
            float dd = dx * dx + dy * dy + dz * dz;
            w[j] = 1.f / (dd + 1e-8f);
            ws += w[j];
        }
#pragma unroll
        for (int j = 0; j < 3; j++) {
            qw[threadIdx.x][j] = w[j] / ws;
            qb[threadIdx.x][j] = bis[j];
        }
    }
    __syncthreads();
    for (int qv = 0; qv < 128; ++qv) {
        float w0 = qw[qv][0], w1 = qw[qv][1], w2 = qw[qv][2];
        const float* f0 = fr + ((long)b * Mr + qb[qv][0]) * C;
        const float* f1 = fr + ((long)b * Mr + qb[qv][1]) * C;
        const float* f2 = fr + ((long)b * Mr + qb[qv][2]) * C;
        long ro = ((long)b * Sq + q0 + qv) * C;
        for (int c = threadIdx.x; c < C; c += blockDim.x)
            out[ro + c] = w0 * f0[c] + w1 * f1[c] + w2 * f2[c];
    }
}

// FP0 skip: [cls(16) | xyz(3) | nrm(3)] width-22 rows
__global__ void fp0_skip_kernel(const float* __restrict__ cls,
                                const float* __restrict__ xyz,
                                const float* __restrict__ nrm,
                                float* __restrict__ sk) {
    int total = BB * NN * 22;
    int stride = gridDim.x * blockDim.x;
    for (int i = blockIdx.x * blockDim.x + threadIdx.x; i < total; i += stride) {
        int c = i % 22;
        int row = i / 22;
        int b = row / NN;
        float v;
        if (c < 16)      v = cls[b * 16 + c];
        else if (c < 19) v = xyz[(long)row * 3 + (c - 16)];
        else             v = nrm[(long)row * 3 + (c - 19)];
        sk[i] = v;
    }
}

__global__ void transpose_kernel(const float* __restrict__ in, float* __restrict__ out) {
    __shared__ float tile[32][33];
    int b = blockIdx.z;
    int n0 = blockIdx.x * 32, c0 = blockIdx.y * 32;
    int tx = threadIdx.x, ty = threadIdx.y;
    tile[ty][tx] = in[((long)b * NN + n0 + ty) * 128 + c0 + tx];
    __syncthreads();
    out[((long)b * 128 + c0 + ty) * NN + n0 + tx] = tile[tx][ty];
}

// ============================================================================
// host driver
// ============================================================================
static void launch_g4(const float* A1, int C1, const float* A2, int C2,
                      const float* W, const float* bias, float* out,
                      int rows, int Cout, int relu) {
    int bd = Cout / 4;
    if (bd < 32) bd = 32;
    if (bd > 128) bd = 128;
    int rt = (rows >= 8192) ? 16 : (rows >= 2048) ? 8 : (rows >= 1024) ? 4 : 2;
    dim3 g((rows + rt - 1) / rt, (Cout + bd * 4 - 1) / (bd * 4));
    size_t sm = (size_t)rt * (C1 + C2) * sizeof(ull);
    switch (rt) {
        case 16: gemm4_kernel<16><<<g, bd, sm>>>(A1, C1, A2, C2, W, bias, out, rows, Cout, relu); break;
        case 8:  gemm4_kernel<8><<<g, bd, sm>>>(A1, C1, A2, C2, W, bias, out, rows, Cout, relu); break;
        case 4:  gemm4_kernel<4><<<g, bd, sm>>>(A1, C1, A2, C2, W, bias, out, rows, Cout, relu); break;
        default: gemm4_kernel<2><<<g, bd, sm>>>(A1, C1, A2, C2, W, bias, out, rows, Cout, relu); break;
    }
}

extern "C" void kernel_launch(void* const* d_in, const int* in_sizes, int n_in,
                              void* d_out, int out_size) {
    const float* x    = (const float*)d_in[0];
    const float* cls  = (const float*)d_in[1];
    const float* W0 = (const float*)d_in[2];  const float* b0 = (const float*)d_in[3];
    const float* W1 = (const float*)d_in[4];  const float* b1 = (const float*)d_in[5];
    const float* W2 = (const float*)d_in[6];  const float* b2 = (const float*)d_in[7];
    const float* W3 = (const float*)d_in[8];  const float* b3 = (const float*)d_in[9];
    const float* F3 = (const float*)d_in[10]; const float* fb3 = (const float*)d_in[11];
    const float* F2 = (const float*)d_in[12]; const float* fb2 = (const float*)d_in[13];
    const float* F1 = (const float*)d_in[14]; const float* fb1 = (const float*)d_in[15];
    const float* F0 = (const float*)d_in[16]; const float* fb0 = (const float*)d_in[17];
    const float* Wseg = (const float*)d_in[18]; const float* bseg = (const float*)d_in[19];

    float* arena = 0; int* iar = 0;
    cudaGetSymbolAddress((void**)&arena, g_arena);
    cudaGetSymbolAddress((void**)&iar, g_iarena);

    float* xyz = arena + OFF_XYZ;
    float* nrm = arena + OFF_NRM;
    float* x1 = arena + OFF_X1; float* x2 = arena + OFF_X2;
    float* x3 = arena + OFF_X3; float* x4 = arena + OFF_X4;
    float* f1 = arena + OFF_F1; float* f2 = arena + OFF_F2;
    float* f3 = arena + OFF_F3; float* f4 = arena + OFF_F4;
    float* g3 = arena + OFF_G3; float* g2 = arena + OFF_G2;
    float* g1 = arena + OFF_G1; float* g0 = arena + OFF_G0;
    float* aproj = arena + OFF_APROJ;
    float* bproj = arena + OFF_BPROJ;
    float* ibuf  = arena + OFF_IBUF;
    float* sk0   = arena + OFF_SK0;
    int* knn = iar;

    cudaFuncSetAttribute((const void*)fps_kernel<512, 8>,
                         cudaFuncAttributeMaxDynamicSharedMemorySize, 3 * NN * 4);

    // launches 1-3: FPS-independent prologue (puts fps1 in profiled slot #4)
    split_kernel<<<(BB * NN + 255) / 256, 256>>>(x, xyz, nrm);                        // 1
    fp0_skip_kernel<<<(BB * NN * 22 + 255) / 256, 256>>>(cls, xyz, nrm, sk0);         // 2
    launch_g4(xyz, 3, nrm, 3, W0, b0, aproj, BB * NN, 64, 0);                         // 3 (SA1 aproj)

    // ---- FPS chain ----
    fps_kernel<512, 8><<<BB, 512, 3 * NN * 4>>>(x, (long)6 * NN, 1, NN, NN, 512, x1); // 4 <- profiled
    fps_kernel<128, 4><<<BB, 128, 3 * 512 * 4>>>(x1, 512 * 3, 3, 1, 512, 256, x2);
    fps_kernel<64, 4><<<BB, 64, 3 * 256 * 4>>>(x2, 256 * 3, 3, 1, 256, 128, x3);
    fps_kernel<32, 4><<<BB, 32, 3 * 128 * 4>>>(x3, 128 * 3, 3, 1, 128, 64, x4);

    // ---- SA1: 4096 -> 512 ----
    knn_kernel<<<BB * 4, 128>>>(x1, 512, xyz, NN, knn);
    launch_g4(x1, 3, 0, 0, W0, 0, bproj, BB * 512, 64, 0);
    gathermax_kernel<<<BB * 512, 64>>>(aproj, bproj, knn, f1, 512, NN, 64);

    // ---- SA2: 512 -> 256 ----
    knn_kernel<<<BB * 2, 128>>>(x2, 256, x1, 512, knn);
    launch_g4(x1, 3, f1, 64, W1, b1, aproj, BB * 512, 128, 0);
    launch_g4(x2, 3, 0, 0, W1, 0, bproj, BB * 256, 128, 0);
    gathermax_kernel<<<BB * 256, 128>>>(aproj, bproj, knn, f2, 256, 512, 128);

    // ---- SA3: 256 -> 128 ----
    knn_kernel<<<BB, 128>>>(x3, 128, x2, 256, knn);
    launch_g4(x2, 3, f2, 128, W2, b2, aproj, BB * 256, 256, 0);
    launch_g4(x3, 3, 0, 0, W2, 0, bproj, BB * 128, 256, 0);
    gathermax_kernel<<<BB * 128, 128>>>(aproj, bproj, knn, f3, 128, 256, 256);

    // ---- SA4: 128 -> 64 ----
    knn_kernel<<<BB, 128>>>(x4, 64, x3, 128, knn);
    launch_g4(x3, 3, f3, 256, W3, b3, aproj, BB * 128, 512, 0);
    launch_g4(x4, 3, 0, 0, W3, 0, bproj, BB * 64, 512, 0);
    gathermax_kernel<<<BB * 64, 128>>>(aproj, bproj, knn, f4, 64, 128, 512);

    // ---- FP3 ----
    interp3_kernel<<<BB, 128>>>(x3, 128, x4, 64, f4, 512, ibuf);
    launch_g4(ibuf, 512, f3, 256, F3, fb3, g3, BB * 128, 512, 1);

    // ---- FP2 ----
    interp3_kernel<<<BB * 2, 128>>>(x2, 256, x3, 128, g3, 512, ibuf);
    launch_g4(ibuf, 512, f2, 128, F2, fb2, g2, BB * 256, 256, 1);

    // ---- FP1 ----
    interp3_kernel<<<BB * 4, 128>>>(x1, 512, x2, 256, g2, 256, ibuf);
    launch_g4(ibuf, 256, f1, 64, F1, fb1, g1, BB * 512, 128, 1);

    // ---- FP0 ----
    interp3_kernel<<<BB * 32, 128>>>(xyz, NN, x1, 512, g1, 128, ibuf);
    launch_g4(ibuf, 128, sk0, 22, F0, fb0, g0, BB * NN, 128, 1);

    // ---- seg head (Cout=50 -> 2-col kernel) ----
    {
        dim3 g((BB * NN + 15) / 16, 1);
        gemm2_kernel<<<g, 32, 16 * 128 * sizeof(float)>>>(
            g0, 128, Wseg, bseg, (float*)d_out, BB * NN, 50, 0);
    }

    // ---- g0 transposed ----
    const int RESULT_SZ = BB * NN * 50;
    const int G0T_SZ = BB * 128 * NN;
    if (out_size >= RESULT_SZ + G0T_SZ) {
        dim3 g(NN / 32, 128 / 32, BB);
        transpose_kernel<<<g, dim3(32, 32)>>>(g0, (float*)d_out + RESULT_SZ);
    }
}